// round 2
// baseline (speedup 1.0000x reference)
#include <cuda_runtime.h>
#include <math.h>

#define S_LEN 2048
#define NB    4
#define NH    6
#define HD    128
#define CDIM  768
#define MTOT  (NB * S_LEN)        // 8192 rows

// Scratch (device globals: allocation-free rule)
__device__ float g_qkv[(size_t)MTOT * 3 * CDIM];   // [8192, 2304]
__device__ float g_att[(size_t)MTOT * CDIM];       // [8192, 768]

// ---------------------------------------------------------------------------
// SGEMM: C[M,N] = A[M,K] @ B[K,N] + bias[N]
// 128x128 block tile, K-tile 8, 256 threads, 8x8 microtile.
// Requires M%128==0, N%128==0, K%8==0 (true for all our shapes).
// ---------------------------------------------------------------------------
__global__ __launch_bounds__(256) void sgemm_bias_kernel(
    const float* __restrict__ A, const float* __restrict__ B,
    const float* __restrict__ bias, float* __restrict__ C,
    int M, int N, int K)
{
    __shared__ float As[8][128];   // transposed: As[k][m]
    __shared__ float Bs[8][128];

    const int tid = threadIdx.x;
    const int tx = tid & 15, ty = tid >> 4;
    const int m0 = blockIdx.y << 7, n0 = blockIdx.x << 7;

    float acc[8][8];
#pragma unroll
    for (int i = 0; i < 8; i++)
#pragma unroll
        for (int j = 0; j < 8; j++) acc[i][j] = 0.f;

    const int arow = tid >> 1, ak = (tid & 1) << 2;     // A: 128 rows x 8 cols
    const int brow = tid >> 5, bcol = (tid & 31) << 2;  // B: 8 rows x 128 cols
    const float* Aptr = A + (size_t)(m0 + arow) * K + ak;
    const float* Bptr = B + (size_t)brow * N + n0 + bcol;

    for (int k0 = 0; k0 < K; k0 += 8) {
        float4 av = *(const float4*)(Aptr + k0);
        float4 bv = *(const float4*)(Bptr + (size_t)k0 * N);
        __syncthreads();
        As[ak + 0][arow] = av.x;
        As[ak + 1][arow] = av.y;
        As[ak + 2][arow] = av.z;
        As[ak + 3][arow] = av.w;
        *(float4*)&Bs[brow][bcol] = bv;
        __syncthreads();
#pragma unroll
        for (int k = 0; k < 8; k++) {
            float a[8], bb[8];
            *(float4*)(a)      = *(const float4*)&As[k][ty * 8];
            *(float4*)(a + 4)  = *(const float4*)&As[k][ty * 8 + 4];
            *(float4*)(bb)     = *(const float4*)&Bs[k][tx * 8];
            *(float4*)(bb + 4) = *(const float4*)&Bs[k][tx * 8 + 4];
#pragma unroll
            for (int i = 0; i < 8; i++)
#pragma unroll
                for (int j = 0; j < 8; j++)
                    acc[i][j] = fmaf(a[i], bb[j], acc[i][j]);
        }
    }

#pragma unroll
    for (int i = 0; i < 8; i++) {
        const int row = m0 + ty * 8 + i;
        float* crow = C + (size_t)row * N + n0 + tx * 8;
        const float* bp = bias + n0 + tx * 8;
#pragma unroll
        for (int j = 0; j < 8; j += 4) {
            float4 o;
            o.x = acc[i][j + 0] + bp[j + 0];
            o.y = acc[i][j + 1] + bp[j + 1];
            o.z = acc[i][j + 2] + bp[j + 2];
            o.w = acc[i][j + 3] + bp[j + 3];
            *(float4*)(crow + j) = o;
        }
    }
}

// ---------------------------------------------------------------------------
// Flash attention (fp32, causal).
// Grid: (S/64, B*H). Block: 256 threads.
// BM=64 query rows per CTA, BN=64 keys per iteration, D=128.
// Thread layout: tr = tid/16 (owns query rows 4*tr..4*tr+3), tc = tid%16.
// S-phase: 4x4 microtile, key cols c = tc + 16*j.
// PV-phase: 4 rows x 8 d-cols (d = tc*4+j and 64+tc*4+j).
// Row reductions via __shfl_xor width 16 (the 16 lanes owning one row).
// ---------------------------------------------------------------------------
#define QS_STR 132     // Q tile stride (64 x 128, padded)
#define KV_STR 129     // K tile stride (odd -> conflict-free per-lane row access)
#define VS_STR 132     // V tile stride (reuses KV buffer)
#define PS_STR 68      // P tile stride (64 x 64, padded)

#define SM_Q   0
#define SM_KV  (64 * QS_STR)                 // 8448
#define SM_P   (SM_KV + 64 * VS_STR)         // KV buffer sized for max(64*129, 64*132)
#define SM_FLT (SM_P + 64 * PS_STR)          // total floats
// SM_FLT = 8448 + 8448 + 4352 = 21248 floats = 84992 bytes

__global__ __launch_bounds__(256) void flash_attn_kernel(
    const float* __restrict__ qkv, float* __restrict__ att)
{
    extern __shared__ float sm[];
    float* Qs = sm + SM_Q;
    float* KVs = sm + SM_KV;
    float* Ps = sm + SM_P;

    const int tid = threadIdx.x;
    const int b = blockIdx.y / NH, h = blockIdx.y % NH;
    const int qm0 = blockIdx.x << 6;
    const float scale = 0.08838834764831845f;   // 1/sqrt(128)

    // Load + pre-scale Q tile [64,128]
    const float* qbase = qkv + (size_t)(b * S_LEN + qm0) * (3 * CDIM) + h * HD;
    for (int i = tid; i < 64 * 32; i += 256) {
        int r = i >> 5, c4 = (i & 31) << 2;
        float4 v = *(const float4*)(qbase + (size_t)r * (3 * CDIM) + c4);
        v.x *= scale; v.y *= scale; v.z *= scale; v.w *= scale;
        *(float4*)&Qs[r * QS_STR + c4] = v;
    }

    const int tc = tid & 15, tr = tid >> 4;
    const int r0 = tr << 2;

    float m_i[4], l_i[4], acc[4][8];
#pragma unroll
    for (int i = 0; i < 4; i++) {
        m_i[i] = -1e30f; l_i[i] = 0.f;
#pragma unroll
        for (int j = 0; j < 8; j++) acc[i][j] = 0.f;
    }

    const int nkb = blockIdx.x + 1;   // causal: only key blocks <= query block
    for (int kb = 0; kb < nkb; kb++) {
        const float* kbase = qkv + (size_t)(b * S_LEN + (kb << 6)) * (3 * CDIM) + CDIM + h * HD;
        __syncthreads();   // protect KV buffer from previous PV reads
        for (int i = tid; i < 64 * 32; i += 256) {
            int r = i >> 5, c4 = (i & 31) << 2;
            float4 v = *(const float4*)(kbase + (size_t)r * (3 * CDIM) + c4);
            KVs[r * KV_STR + c4 + 0] = v.x;
            KVs[r * KV_STR + c4 + 1] = v.y;
            KVs[r * KV_STR + c4 + 2] = v.z;
            KVs[r * KV_STR + c4 + 3] = v.w;
        }
        __syncthreads();

        // S = Q K^T  (4 rows x 4 cols per thread, cols = tc + 16*j)
        float s[4][4];
#pragma unroll
        for (int i = 0; i < 4; i++)
#pragma unroll
            for (int j = 0; j < 4; j++) s[i][j] = 0.f;

#pragma unroll 4
        for (int d = 0; d < HD; d++) {
            float q0 = Qs[(r0 + 0) * QS_STR + d];
            float q1 = Qs[(r0 + 1) * QS_STR + d];
            float q2 = Qs[(r0 + 2) * QS_STR + d];
            float q3 = Qs[(r0 + 3) * QS_STR + d];
#pragma unroll
            for (int j = 0; j < 4; j++) {
                float kk = KVs[(tc + 16 * j) * KV_STR + d];
                s[0][j] = fmaf(q0, kk, s[0][j]);
                s[1][j] = fmaf(q1, kk, s[1][j]);
                s[2][j] = fmaf(q2, kk, s[2][j]);
                s[3][j] = fmaf(q3, kk, s[3][j]);
            }
        }

        if (kb == blockIdx.x) {   // diagonal block: mask local c > local r
#pragma unroll
            for (int i = 0; i < 4; i++)
#pragma unroll
                for (int j = 0; j < 4; j++)
                    if ((tc + 16 * j) > (r0 + i)) s[i][j] = -1e30f;
        }

        // Online softmax per row
#pragma unroll
        for (int i = 0; i < 4; i++) {
            float mloc = fmaxf(fmaxf(s[i][0], s[i][1]), fmaxf(s[i][2], s[i][3]));
#pragma unroll
            for (int off = 8; off >= 1; off >>= 1)
                mloc = fmaxf(mloc, __shfl_xor_sync(0xffffffffu, mloc, off, 16));
            float mnew = fmaxf(m_i[i], mloc);
            float alph = __expf(m_i[i] - mnew);
            m_i[i] = mnew;
            float rs = 0.f;
#pragma unroll
            for (int j = 0; j < 4; j++) {
                float p = __expf(s[i][j] - mnew);
                Ps[(r0 + i) * PS_STR + tc + 16 * j] = p;
                rs += p;
            }
#pragma unroll
            for (int off = 8; off >= 1; off >>= 1)
                rs += __shfl_xor_sync(0xffffffffu, rs, off, 16);
            l_i[i] = l_i[i] * alph + rs;
#pragma unroll
            for (int j = 0; j < 8; j++) acc[i][j] *= alph;
        }

        __syncthreads();   // KV reads done, Ps written
        // Load V tile [64,128] row-major into KV buffer
        const float* vbase = kbase + CDIM;
        for (int i = tid; i < 64 * 32; i += 256) {
            int r = i >> 5, c4 = (i & 31) << 2;
            *(float4*)&KVs[r * VS_STR + c4] =
                *(const float4*)(vbase + (size_t)r * (3 * CDIM) + c4);
        }
        __syncthreads();

        // O += P @ V   (4 rows x 8 d-cols per thread; d = tc*4+j, 64+tc*4+j)
#pragma unroll 2
        for (int c = 0; c < 64; c++) {
            float4 v0 = *(const float4*)&KVs[c * VS_STR + (tc << 2)];
            float4 v1 = *(const float4*)&KVs[c * VS_STR + 64 + (tc << 2)];
#pragma unroll
            for (int i = 0; i < 4; i++) {
                float p = Ps[(r0 + i) * PS_STR + c];
                acc[i][0] = fmaf(p, v0.x, acc[i][0]);
                acc[i][1] = fmaf(p, v0.y, acc[i][1]);
                acc[i][2] = fmaf(p, v0.z, acc[i][2]);
                acc[i][3] = fmaf(p, v0.w, acc[i][3]);
                acc[i][4] = fmaf(p, v1.x, acc[i][4]);
                acc[i][5] = fmaf(p, v1.y, acc[i][5]);
                acc[i][6] = fmaf(p, v1.z, acc[i][6]);
                acc[i][7] = fmaf(p, v1.w, acc[i][7]);
            }
        }
    }

    // Epilogue: O /= l, write to g_att [B*S, C] with head offset
    float* obase = att + (size_t)(b * S_LEN + qm0) * CDIM + h * HD;
#pragma unroll
    for (int i = 0; i < 4; i++) {
        float inv = 1.f / l_i[i];
        float4 o0, o1;
        o0.x = acc[i][0] * inv; o0.y = acc[i][1] * inv;
        o0.z = acc[i][2] * inv; o0.w = acc[i][3] * inv;
        o1.x = acc[i][4] * inv; o1.y = acc[i][5] * inv;
        o1.z = acc[i][6] * inv; o1.w = acc[i][7] * inv;
        *(float4*)(obase + (size_t)(r0 + i) * CDIM + (tc << 2)) = o0;
        *(float4*)(obase + (size_t)(r0 + i) * CDIM + 64 + (tc << 2)) = o1;
    }
}

// ---------------------------------------------------------------------------
extern "C" void kernel_launch(void* const* d_in, const int* in_sizes, int n_in,
                              void* d_out, int out_size)
{
    const float* x      = (const float*)d_in[0];
    const float* w_attn = (const float*)d_in[1];
    const float* b_attn = (const float*)d_in[2];
    const float* w_proj = (const float*)d_in[3];
    const float* b_proj = (const float*)d_in[4];
    float* out = (float*)d_out;

    float* qkv_ptr = nullptr;
    float* att_ptr = nullptr;
    cudaGetSymbolAddress((void**)&qkv_ptr, g_qkv);
    cudaGetSymbolAddress((void**)&att_ptr, g_att);

    cudaFuncSetAttribute(flash_attn_kernel,
                         cudaFuncAttributeMaxDynamicSharedMemorySize,
                         SM_FLT * (int)sizeof(float));

    // 1) QKV projection: [8192,768] @ [768,2304] + b
    dim3 g1(3 * CDIM / 128, MTOT / 128);
    sgemm_bias_kernel<<<g1, 256>>>(x, w_attn, b_attn, qkv_ptr,
                                   MTOT, 3 * CDIM, CDIM);

    // 2) Causal flash attention
    dim3 g2(S_LEN / 64, NB * NH);
    flash_attn_kernel<<<g2, 256, SM_FLT * (int)sizeof(float)>>>(qkv_ptr, att_ptr);

    // 3) Output projection: [8192,768] @ [768,768] + b
    dim3 g3(CDIM / 128, MTOT / 128);
    sgemm_bias_kernel<<<g3, 256>>>(att_ptr, w_proj, b_proj, out,
                                   MTOT, CDIM, CDIM);
}

// round 4
// speedup vs baseline: 1.3516x; 1.3516x over previous
#include <cuda_runtime.h>
#include <cuda_bf16.h>
#include <cstdint>
#include <math.h>

#define S_LEN 2048
#define NB    4
#define NH    6
#define HD    128
#define CDIM  768
#define MTOT  (NB * S_LEN)        // 8192 rows
#define KP    (3 * CDIM)          // 2304 = split-K for bf16x3 GEMM
#define GCH   64                  // GEMM K-chunk (bf16 elems)
#define NCH   (KP / GCH)          // 36 chunks

// ---------------------------------------------------------------------------
// Scratch (device globals: allocation-free rule)
// ---------------------------------------------------------------------------
__device__ float g_qkv[(size_t)MTOT * 3 * CDIM];            // [8192, 2304] f32
__device__ float g_att[(size_t)MTOT * CDIM];                // [8192, 768]  f32
__device__ __nv_bfloat16 g_a1 [(size_t)MTOT * KP];          // A split [8192, 2304]
__device__ __nv_bfloat16 g_wt1[(size_t)(3 * CDIM) * KP];    // W_attn^T split [2304, 2304]
__device__ __nv_bfloat16 g_wt2[(size_t)CDIM * KP];          // W_proj^T split [768, 2304]

__device__ __forceinline__ uint32_t smem_u32(const void* p) {
    uint32_t a;
    asm("{ .reg .u64 t; cvta.to.shared.u64 t, %1; cvt.u32.u64 %0, t; }" : "=r"(a) : "l"(p));
    return a;
}

// ---------------------------------------------------------------------------
// Split kernels.
// A' = [Ah | Al | Ah] along K (row-major activations)
// B' = [Bh | Bh | Bl] along K (K-major weights)  => A'.B' = AhBh + AlBh + AhBl
// ---------------------------------------------------------------------------
__global__ void asplit_kernel(const float* __restrict__ src,
                              __nv_bfloat16* __restrict__ dst, int total, int K)
{
    int idx = blockIdx.x * blockDim.x + threadIdx.x;
    if (idx >= total) return;
    int m = idx / K, k = idx - m * K;
    float v = src[idx];
    __nv_bfloat16 h = __float2bfloat16_rn(v);
    __nv_bfloat16 l = __float2bfloat16_rn(v - __bfloat162float(h));
    __nv_bfloat16* d = dst + (size_t)m * (3 * K) + k;
    d[0]     = h;
    d[K]     = l;
    d[2 * K] = h;
}

// W[K,N] f32 -> Wt[N, 3K] bf16 K-major: [hi | hi | lo]
__global__ void wsplit_kernel(const float* __restrict__ W,
                              __nv_bfloat16* __restrict__ Wt, int K, int N)
{
    __shared__ float t[32][33];
    int kb = blockIdx.x * 32, nb = blockIdx.y * 32;
    int tx = threadIdx.x, ty = threadIdx.y;    // block (32, 8)
    for (int i = ty; i < 32; i += 8)
        t[i][tx] = W[(size_t)(kb + i) * N + nb + tx];
    __syncthreads();
    for (int i = ty; i < 32; i += 8) {
        int n = nb + i, k = kb + tx;
        float v = t[tx][i];
        __nv_bfloat16 h = __float2bfloat16_rn(v);
        __nv_bfloat16 l = __float2bfloat16_rn(v - __bfloat162float(h));
        __nv_bfloat16* d = Wt + (size_t)n * (3 * K) + k;
        d[0]     = h;
        d[K]     = h;
        d[2 * K] = l;
    }
}

// ---------------------------------------------------------------------------
// bf16 mma.sync GEMM: C[M, Nt] = A1[M, KP] @ Bt[Nt, KP]^T + bias
// CTA tile 128x128, K-chunk 64, 2-stage cp.async. 8 warps (2m x 4n), warp
// tile 64x32 -> 4x4 grid of m16n8k16 mma. SMEM rows padded to 72 bf16 (144B)
// -> ldmatrix conflict-free (row stride 36 words; 8 rows hit banks 4r..4r+3).
// ---------------------------------------------------------------------------
#define AST 72                      // padded row, bf16 elems
#define STAGE_B  (128 * AST * 2)    // 18432 bytes per operand tile
#define GEMM_SMEM (4 * STAGE_B)     // A0 A1 B0 B1 = 73728

__device__ __forceinline__ void g_load_tile(uint32_t sm_tile,
                                            const __nv_bfloat16* g, int k0, int tid)
{
#pragma unroll
    for (int i = 0; i < 4; i++) {
        int s = i * 256 + tid;
        int r = s >> 3, cg = s & 7;               // 128 rows x 8 16B-groups
        uint32_t dst = sm_tile + r * 144 + cg * 16;
        const void* src = g + (size_t)r * KP + k0 + cg * 8;
        asm volatile("cp.async.cg.shared.global [%0], [%1], 16;" :: "r"(dst), "l"(src));
    }
}

__device__ __forceinline__ void ldm_x4(uint32_t addr, uint32_t& r0, uint32_t& r1,
                                       uint32_t& r2, uint32_t& r3)
{
    asm volatile("ldmatrix.sync.aligned.m8n8.x4.shared.b16 {%0,%1,%2,%3}, [%4];"
                 : "=r"(r0), "=r"(r1), "=r"(r2), "=r"(r3) : "r"(addr));
}

__device__ __forceinline__ void mma16816(float* c, const uint32_t* a, const uint32_t* b)
{
    asm volatile(
        "mma.sync.aligned.m16n8k16.row.col.f32.bf16.bf16.f32 "
        "{%0,%1,%2,%3}, {%4,%5,%6,%7}, {%8,%9}, {%0,%1,%2,%3};"
        : "+f"(c[0]), "+f"(c[1]), "+f"(c[2]), "+f"(c[3])
        : "r"(a[0]), "r"(a[1]), "r"(a[2]), "r"(a[3]), "r"(b[0]), "r"(b[1]));
}

__global__ __launch_bounds__(256, 2) void mma_gemm_kernel(
    const __nv_bfloat16* __restrict__ A1, const __nv_bfloat16* __restrict__ Bt,
    const float* __restrict__ bias, float* __restrict__ C, int Nt)
{
    extern __shared__ char smem[];
    const uint32_t sb = smem_u32(smem);
    const int tid = threadIdx.x, wid = tid >> 5, lane = tid & 31;
    const int m0 = blockIdx.y << 7, n0 = blockIdx.x << 7;
    const int wm = wid & 1, wn = wid >> 1;          // warp tile: rows wm*64, cols wn*32

    const uint32_t sA[2] = { sb,               sb + STAGE_B };
    const uint32_t sB[2] = { sb + 2 * STAGE_B, sb + 3 * STAGE_B };

    const __nv_bfloat16* Ag = A1 + (size_t)m0 * KP;
    const __nv_bfloat16* Bg = Bt + (size_t)n0 * KP;

    float acc[4][4][4];
#pragma unroll
    for (int i = 0; i < 4; i++)
#pragma unroll
        for (int j = 0; j < 4; j++)
#pragma unroll
            for (int r = 0; r < 4; r++) acc[i][j][r] = 0.f;

    // ldmatrix source addresses (chunk-buffer relative)
    // A: lanes 0-15 -> rows (m)lane, k-half 0; lanes 16-31 -> same rows, k-half 1
    const int a_row = (wm << 6) + (lane & 15);
    const int a_kof = (lane >> 4) << 3;
    // B: g = lane>>3, r = lane&7 ; n += 8*(g>>1), k += 8*(g&1)
    const int b_row = (wn << 5) + (lane & 7) + (((lane >> 3) >> 1) << 3);
    const int b_kof = ((lane >> 3) & 1) << 3;

    // prologue
    g_load_tile(sA[0], Ag, 0, tid);
    g_load_tile(sB[0], Bg, 0, tid);
    asm volatile("cp.async.commit_group;" ::: "memory");

    for (int c = 0; c < NCH; c++) {
        const int cur = c & 1;
        if (c + 1 < NCH) {
            const int nb = (c + 1) & 1;
            g_load_tile(sA[nb], Ag, (c + 1) * GCH, tid);
            g_load_tile(sB[nb], Bg, (c + 1) * GCH, tid);
            asm volatile("cp.async.commit_group;" ::: "memory");
            asm volatile("cp.async.wait_group 1;" ::: "memory");
        } else {
            asm volatile("cp.async.wait_group 0;" ::: "memory");
        }
        __syncthreads();

#pragma unroll
        for (int ks = 0; ks < 4; ks++) {           // 4 x k16 within chunk
            const int kbase = ks << 4;
            uint32_t a[4][4];
#pragma unroll
            for (int mi = 0; mi < 4; mi++) {
                uint32_t addr = sA[cur] + (uint32_t)(a_row + mi * 16) * 144
                              + (uint32_t)(kbase + a_kof) * 2;
                ldm_x4(addr, a[mi][0], a[mi][1], a[mi][2], a[mi][3]);
            }
            uint32_t b[4][2];
#pragma unroll
            for (int nb2 = 0; nb2 < 2; nb2++) {    // two n16 groups -> 4 n8 tiles
                uint32_t addr = sB[cur] + (uint32_t)(b_row + nb2 * 16) * 144
                              + (uint32_t)(kbase + b_kof) * 2;
                uint32_t t0, t1, t2, t3;
                ldm_x4(addr, t0, t1, t2, t3);
                b[nb2 * 2 + 0][0] = t0; b[nb2 * 2 + 0][1] = t1;
                b[nb2 * 2 + 1][0] = t2; b[nb2 * 2 + 1][1] = t3;
            }
#pragma unroll
            for (int mi = 0; mi < 4; mi++)
#pragma unroll
                for (int ni = 0; ni < 4; ni++)
                    mma16816(acc[mi][ni], a[mi], b[ni]);
        }
        __syncthreads();
    }

    // Epilogue: direct register -> gmem, add bias
    const int r_top = m0 + (wm << 6) + (lane >> 2);
    const int c_base = n0 + (wn << 5) + ((lane & 3) << 1);
#pragma unroll
    for (int mi = 0; mi < 4; mi++) {
#pragma unroll
        for (int ni = 0; ni < 4; ni++) {
            const int col = c_base + ni * 8;
            const float b0 = bias[col], b1 = bias[col + 1];
            const int row0 = r_top + mi * 16;
            float2 v0 = { acc[mi][ni][0] + b0, acc[mi][ni][1] + b1 };
            float2 v1 = { acc[mi][ni][2] + b0, acc[mi][ni][3] + b1 };
            *(float2*)&C[(size_t)row0 * Nt + col]       = v0;
            *(float2*)&C[(size_t)(row0 + 8) * Nt + col] = v1;
        }
    }
}

// ---------------------------------------------------------------------------
// Flash attention (fp32, causal) — unchanged from round 2 baseline.
// ---------------------------------------------------------------------------
#define QS_STR 132
#define KV_STR 129
#define VS_STR 132
#define PS_STR 68

#define SM_Q   0
#define SM_KV  (64 * QS_STR)
#define SM_P   (SM_KV + 64 * VS_STR)
#define SM_FLT (SM_P + 64 * PS_STR)

__global__ __launch_bounds__(256) void flash_attn_kernel(
    const float* __restrict__ qkv, float* __restrict__ att)
{
    extern __shared__ float sm[];
    float* Qs = sm + SM_Q;
    float* KVs = sm + SM_KV;
    float* Ps = sm + SM_P;

    const int tid = threadIdx.x;
    const int b = blockIdx.y / NH, h = blockIdx.y % NH;
    const int qm0 = blockIdx.x << 6;
    const float scale = 0.08838834764831845f;

    const float* qbase = qkv + (size_t)(b * S_LEN + qm0) * (3 * CDIM) + h * HD;
    for (int i = tid; i < 64 * 32; i += 256) {
        int r = i >> 5, c4 = (i & 31) << 2;
        float4 v = *(const float4*)(qbase + (size_t)r * (3 * CDIM) + c4);
        v.x *= scale; v.y *= scale; v.z *= scale; v.w *= scale;
        *(float4*)&Qs[r * QS_STR + c4] = v;
    }

    const int tc = tid & 15, tr = tid >> 4;
    const int r0 = tr << 2;

    float m_i[4], l_i[4], acc[4][8];
#pragma unroll
    for (int i = 0; i < 4; i++) {
        m_i[i] = -1e30f; l_i[i] = 0.f;
#pragma unroll
        for (int j = 0; j < 8; j++) acc[i][j] = 0.f;
    }

    const int nkb = blockIdx.x + 1;
    for (int kb = 0; kb < nkb; kb++) {
        const float* kbase = qkv + (size_t)(b * S_LEN + (kb << 6)) * (3 * CDIM) + CDIM + h * HD;
        __syncthreads();
        for (int i = tid; i < 64 * 32; i += 256) {
            int r = i >> 5, c4 = (i & 31) << 2;
            float4 v = *(const float4*)(kbase + (size_t)r * (3 * CDIM) + c4);
            KVs[r * KV_STR + c4 + 0] = v.x;
            KVs[r * KV_STR + c4 + 1] = v.y;
            KVs[r * KV_STR + c4 + 2] = v.z;
            KVs[r * KV_STR + c4 + 3] = v.w;
        }
        __syncthreads();

        float s[4][4];
#pragma unroll
        for (int i = 0; i < 4; i++)
#pragma unroll
            for (int j = 0; j < 4; j++) s[i][j] = 0.f;

#pragma unroll 4
        for (int d = 0; d < HD; d++) {
            float q0 = Qs[(r0 + 0) * QS_STR + d];
            float q1 = Qs[(r0 + 1) * QS_STR + d];
            float q2 = Qs[(r0 + 2) * QS_STR + d];
            float q3 = Qs[(r0 + 3) * QS_STR + d];
#pragma unroll
            for (int j = 0; j < 4; j++) {
                float kk = KVs[(tc + 16 * j) * KV_STR + d];
                s[0][j] = fmaf(q0, kk, s[0][j]);
                s[1][j] = fmaf(q1, kk, s[1][j]);
                s[2][j] = fmaf(q2, kk, s[2][j]);
                s[3][j] = fmaf(q3, kk, s[3][j]);
            }
        }

        if (kb == blockIdx.x) {
#pragma unroll
            for (int i = 0; i < 4; i++)
#pragma unroll
                for (int j = 0; j < 4; j++)
                    if ((tc + 16 * j) > (r0 + i)) s[i][j] = -1e30f;
        }

#pragma unroll
        for (int i = 0; i < 4; i++) {
            float mloc = fmaxf(fmaxf(s[i][0], s[i][1]), fmaxf(s[i][2], s[i][3]));
#pragma unroll
            for (int off = 8; off >= 1; off >>= 1)
                mloc = fmaxf(mloc, __shfl_xor_sync(0xffffffffu, mloc, off, 16));
            float mnew = fmaxf(m_i[i], mloc);
            float alph = __expf(m_i[i] - mnew);
            m_i[i] = mnew;
            float rs = 0.f;
#pragma unroll
            for (int j = 0; j < 4; j++) {
                float p = __expf(s[i][j] - mnew);
                Ps[(r0 + i) * PS_STR + tc + 16 * j] = p;
                rs += p;
            }
#pragma unroll
            for (int off = 8; off >= 1; off >>= 1)
                rs += __shfl_xor_sync(0xffffffffu, rs, off, 16);
            l_i[i] = l_i[i] * alph + rs;
#pragma unroll
            for (int j = 0; j < 8; j++) acc[i][j] *= alph;
        }

        __syncthreads();
        const float* vbase = kbase + CDIM;
        for (int i = tid; i < 64 * 32; i += 256) {
            int r = i >> 5, c4 = (i & 31) << 2;
            *(float4*)&KVs[r * VS_STR + c4] =
                *(const float4*)(vbase + (size_t)r * (3 * CDIM) + c4);
        }
        __syncthreads();

#pragma unroll 2
        for (int c = 0; c < 64; c++) {
            float4 v0 = *(const float4*)&KVs[c * VS_STR + (tc << 2)];
            float4 v1 = *(const float4*)&KVs[c * VS_STR + 64 + (tc << 2)];
#pragma unroll
            for (int i = 0; i < 4; i++) {
                float p = Ps[(r0 + i) * PS_STR + c];
                acc[i][0] = fmaf(p, v0.x, acc[i][0]);
                acc[i][1] = fmaf(p, v0.y, acc[i][1]);
                acc[i][2] = fmaf(p, v0.z, acc[i][2]);
                acc[i][3] = fmaf(p, v0.w, acc[i][3]);
                acc[i][4] = fmaf(p, v1.x, acc[i][4]);
                acc[i][5] = fmaf(p, v1.y, acc[i][5]);
                acc[i][6] = fmaf(p, v1.z, acc[i][6]);
                acc[i][7] = fmaf(p, v1.w, acc[i][7]);
            }
        }
    }

    float* obase = att + (size_t)(b * S_LEN + qm0) * CDIM + h * HD;
#pragma unroll
    for (int i = 0; i < 4; i++) {
        float inv = 1.f / l_i[i];
        float4 o0, o1;
        o0.x = acc[i][0] * inv; o0.y = acc[i][1] * inv;
        o0.z = acc[i][2] * inv; o0.w = acc[i][3] * inv;
        o1.x = acc[i][4] * inv; o1.y = acc[i][5] * inv;
        o1.z = acc[i][6] * inv; o1.w = acc[i][7] * inv;
        *(float4*)(obase + (size_t)(r0 + i) * CDIM + (tc << 2)) = o0;
        *(float4*)(obase + (size_t)(r0 + i) * CDIM + 64 + (tc << 2)) = o1;
    }
}

// ---------------------------------------------------------------------------
extern "C" void kernel_launch(void* const* d_in, const int* in_sizes, int n_in,
                              void* d_out, int out_size)
{
    const float* x      = (const float*)d_in[0];
    const float* w_attn = (const float*)d_in[1];
    const float* b_attn = (const float*)d_in[2];
    const float* w_proj = (const float*)d_in[3];
    const float* b_proj = (const float*)d_in[4];
    float* out = (float*)d_out;

    float *qkv_ptr = nullptr, *att_ptr = nullptr;
    __nv_bfloat16 *a1 = nullptr, *wt1 = nullptr, *wt2 = nullptr;
    cudaGetSymbolAddress((void**)&qkv_ptr, g_qkv);
    cudaGetSymbolAddress((void**)&att_ptr, g_att);
    cudaGetSymbolAddress((void**)&a1,  g_a1);
    cudaGetSymbolAddress((void**)&wt1, g_wt1);
    cudaGetSymbolAddress((void**)&wt2, g_wt2);

    cudaFuncSetAttribute(flash_attn_kernel,
                         cudaFuncAttributeMaxDynamicSharedMemorySize,
                         SM_FLT * (int)sizeof(float));
    cudaFuncSetAttribute(mma_gemm_kernel,
                         cudaFuncAttributeMaxDynamicSharedMemorySize, GEMM_SMEM);

    // --- Stage 1: QKV = x @ w_attn + b (bf16x3 tensor cores) ---
    asplit_kernel<<<(MTOT * CDIM + 255) / 256, 256>>>(x, a1, MTOT * CDIM, CDIM);
    {
        dim3 gt(CDIM / 32, (3 * CDIM) / 32), bt(32, 8);
        wsplit_kernel<<<gt, bt>>>(w_attn, wt1, CDIM, 3 * CDIM);
    }
    {
        dim3 g(3 * CDIM / 128, MTOT / 128);
        mma_gemm_kernel<<<g, 256, GEMM_SMEM>>>(a1, wt1, b_attn, qkv_ptr, 3 * CDIM);
    }

    // --- Stage 2: causal flash attention (fp32) ---
    {
        dim3 g(S_LEN / 64, NB * NH);
        flash_attn_kernel<<<g, 256, SM_FLT * (int)sizeof(float)>>>(qkv_ptr, att_ptr);
    }

    // --- Stage 3: out = att @ w_proj + b (bf16x3 tensor cores) ---
    asplit_kernel<<<(MTOT * CDIM + 255) / 256, 256>>>(att_ptr, a1, MTOT * CDIM, CDIM);
    {
        dim3 gt(CDIM / 32, CDIM / 32), bt(32, 8);
        wsplit_kernel<<<gt, bt>>>(w_proj, wt2, CDIM, CDIM);
    }
    {
        dim3 g(CDIM / 128, MTOT / 128);
        mma_gemm_kernel<<<g, 256, GEMM_SMEM>>>(a1, wt2, b_proj, out, CDIM);
    }
}

// round 5
// speedup vs baseline: 2.2638x; 1.6749x over previous
#include <cuda_runtime.h>
#include <cuda_bf16.h>
#include <cstdint>
#include <math.h>

#define S_LEN 2048
#define NB    4
#define NH    6
#define HD    128
#define CDIM  768
#define MTOT  (NB * S_LEN)        // 8192 rows
#define KP    (3 * CDIM)          // 2304 = split-K for bf16x3 GEMM
#define GCH   64                  // GEMM K-chunk (bf16 elems)
#define NCH   (KP / GCH)          // 36 chunks

// ---------------------------------------------------------------------------
// Scratch (device globals: allocation-free rule)
// ---------------------------------------------------------------------------
__device__ float g_qkv[(size_t)MTOT * 3 * CDIM];            // [8192, 2304] f32
__device__ float g_att[(size_t)MTOT * CDIM];                // [8192, 768]  f32
__device__ __nv_bfloat16 g_a1 [(size_t)MTOT * KP];          // A split [8192, 2304]
__device__ __nv_bfloat16 g_wt1[(size_t)(3 * CDIM) * KP];    // W_attn^T split
__device__ __nv_bfloat16 g_wt2[(size_t)CDIM * KP];          // W_proj^T split

__device__ __forceinline__ uint32_t smem_u32(const void* p) {
    uint32_t a;
    asm("{ .reg .u64 t; cvta.to.shared.u64 t, %1; cvt.u32.u64 %0, t; }" : "=r"(a) : "l"(p));
    return a;
}
__device__ __forceinline__ void ldm_x4(uint32_t addr, uint32_t& r0, uint32_t& r1,
                                       uint32_t& r2, uint32_t& r3)
{
    asm volatile("ldmatrix.sync.aligned.m8n8.x4.shared.b16 {%0,%1,%2,%3}, [%4];"
                 : "=r"(r0), "=r"(r1), "=r"(r2), "=r"(r3) : "r"(addr));
}
__device__ __forceinline__ void ldm_x4_t(uint32_t addr, uint32_t& r0, uint32_t& r1,
                                         uint32_t& r2, uint32_t& r3)
{
    asm volatile("ldmatrix.sync.aligned.m8n8.x4.trans.shared.b16 {%0,%1,%2,%3}, [%4];"
                 : "=r"(r0), "=r"(r1), "=r"(r2), "=r"(r3) : "r"(addr));
}
__device__ __forceinline__ void mma16816(float* c, const uint32_t* a, const uint32_t* b)
{
    asm volatile(
        "mma.sync.aligned.m16n8k16.row.col.f32.bf16.bf16.f32 "
        "{%0,%1,%2,%3}, {%4,%5,%6,%7}, {%8,%9}, {%0,%1,%2,%3};"
        : "+f"(c[0]), "+f"(c[1]), "+f"(c[2]), "+f"(c[3])
        : "r"(a[0]), "r"(a[1]), "r"(a[2]), "r"(a[3]), "r"(b[0]), "r"(b[1]));
}
__device__ __forceinline__ uint32_t pack_bf(__nv_bfloat16 lo, __nv_bfloat16 hi) {
    __nv_bfloat162 t(lo, hi);
    return *(uint32_t*)&t;
}

// ---------------------------------------------------------------------------
// Split kernels. A' = [Ah|Al|Ah], B' = [Bh|Bh|Bl] => AhBh + AlBh + AhBl
// ---------------------------------------------------------------------------
__global__ void asplit_kernel(const float* __restrict__ src,
                              __nv_bfloat16* __restrict__ dst, int total, int K)
{
    int idx = blockIdx.x * blockDim.x + threadIdx.x;
    if (idx >= total) return;
    int m = idx / K, k = idx - m * K;
    float v = src[idx];
    __nv_bfloat16 h = __float2bfloat16_rn(v);
    __nv_bfloat16 l = __float2bfloat16_rn(v - __bfloat162float(h));
    __nv_bfloat16* d = dst + (size_t)m * (3 * K) + k;
    d[0]     = h;
    d[K]     = l;
    d[2 * K] = h;
}

__global__ void wsplit_kernel(const float* __restrict__ W,
                              __nv_bfloat16* __restrict__ Wt, int K, int N)
{
    __shared__ float t[32][33];
    int kb = blockIdx.x * 32, nb = blockIdx.y * 32;
    int tx = threadIdx.x, ty = threadIdx.y;    // block (32, 8)
    for (int i = ty; i < 32; i += 8)
        t[i][tx] = W[(size_t)(kb + i) * N + nb + tx];
    __syncthreads();
    for (int i = ty; i < 32; i += 8) {
        int n = nb + i, k = kb + tx;
        float v = t[tx][i];
        __nv_bfloat16 h = __float2bfloat16_rn(v);
        __nv_bfloat16 l = __float2bfloat16_rn(v - __bfloat162float(h));
        __nv_bfloat16* d = Wt + (size_t)n * (3 * K) + k;
        d[0]     = h;
        d[K]     = h;
        d[2 * K] = l;
    }
}

// ---------------------------------------------------------------------------
// bf16 mma.sync GEMM (unchanged from round 4 — measured ~300 TF/s)
// ---------------------------------------------------------------------------
#define AST 72
#define STAGE_B  (128 * AST * 2)
#define GEMM_SMEM (4 * STAGE_B)

__device__ __forceinline__ void g_load_tile(uint32_t sm_tile,
                                            const __nv_bfloat16* g, int k0, int tid)
{
#pragma unroll
    for (int i = 0; i < 4; i++) {
        int s = i * 256 + tid;
        int r = s >> 3, cg = s & 7;
        uint32_t dst = sm_tile + r * 144 + cg * 16;
        const void* src = g + (size_t)r * KP + k0 + cg * 8;
        asm volatile("cp.async.cg.shared.global [%0], [%1], 16;" :: "r"(dst), "l"(src));
    }
}

__global__ __launch_bounds__(256, 2) void mma_gemm_kernel(
    const __nv_bfloat16* __restrict__ A1, const __nv_bfloat16* __restrict__ Bt,
    const float* __restrict__ bias, float* __restrict__ C, int Nt)
{
    extern __shared__ char smem[];
    const uint32_t sb = smem_u32(smem);
    const int tid = threadIdx.x, wid = tid >> 5, lane = tid & 31;
    const int m0 = blockIdx.y << 7, n0 = blockIdx.x << 7;
    const int wm = wid & 1, wn = wid >> 1;

    const uint32_t sA[2] = { sb,               sb + STAGE_B };
    const uint32_t sB[2] = { sb + 2 * STAGE_B, sb + 3 * STAGE_B };

    const __nv_bfloat16* Ag = A1 + (size_t)m0 * KP;
    const __nv_bfloat16* Bg = Bt + (size_t)n0 * KP;

    float acc[4][4][4];
#pragma unroll
    for (int i = 0; i < 4; i++)
#pragma unroll
        for (int j = 0; j < 4; j++)
#pragma unroll
            for (int r = 0; r < 4; r++) acc[i][j][r] = 0.f;

    const int a_row = (wm << 6) + (lane & 15);
    const int a_kof = (lane >> 4) << 3;
    const int b_row = (wn << 5) + (lane & 7) + (((lane >> 3) >> 1) << 3);
    const int b_kof = ((lane >> 3) & 1) << 3;

    g_load_tile(sA[0], Ag, 0, tid);
    g_load_tile(sB[0], Bg, 0, tid);
    asm volatile("cp.async.commit_group;" ::: "memory");

    for (int c = 0; c < NCH; c++) {
        const int cur = c & 1;
        if (c + 1 < NCH) {
            const int nb = (c + 1) & 1;
            g_load_tile(sA[nb], Ag, (c + 1) * GCH, tid);
            g_load_tile(sB[nb], Bg, (c + 1) * GCH, tid);
            asm volatile("cp.async.commit_group;" ::: "memory");
            asm volatile("cp.async.wait_group 1;" ::: "memory");
        } else {
            asm volatile("cp.async.wait_group 0;" ::: "memory");
        }
        __syncthreads();

#pragma unroll
        for (int ks = 0; ks < 4; ks++) {
            const int kbase = ks << 4;
            uint32_t a[4][4];
#pragma unroll
            for (int mi = 0; mi < 4; mi++) {
                uint32_t addr = sA[cur] + (uint32_t)(a_row + mi * 16) * 144
                              + (uint32_t)(kbase + a_kof) * 2;
                ldm_x4(addr, a[mi][0], a[mi][1], a[mi][2], a[mi][3]);
            }
            uint32_t b[4][2];
#pragma unroll
            for (int nb2 = 0; nb2 < 2; nb2++) {
                uint32_t addr = sB[cur] + (uint32_t)(b_row + nb2 * 16) * 144
                              + (uint32_t)(kbase + b_kof) * 2;
                uint32_t t0, t1, t2, t3;
                ldm_x4(addr, t0, t1, t2, t3);
                b[nb2 * 2 + 0][0] = t0; b[nb2 * 2 + 0][1] = t1;
                b[nb2 * 2 + 1][0] = t2; b[nb2 * 2 + 1][1] = t3;
            }
#pragma unroll
            for (int mi = 0; mi < 4; mi++)
#pragma unroll
                for (int ni = 0; ni < 4; ni++)
                    mma16816(acc[mi][ni], a[mi], b[ni]);
        }
        __syncthreads();
    }

    const int r_top = m0 + (wm << 6) + (lane >> 2);
    const int c_base = n0 + (wn << 5) + ((lane & 3) << 1);
#pragma unroll
    for (int mi = 0; mi < 4; mi++) {
#pragma unroll
        for (int ni = 0; ni < 4; ni++) {
            const int col = c_base + ni * 8;
            const float b0 = bias[col], b1 = bias[col + 1];
            const int row0 = r_top + mi * 16;
            float2 v0 = { acc[mi][ni][0] + b0, acc[mi][ni][1] + b1 };
            float2 v1 = { acc[mi][ni][2] + b0, acc[mi][ni][3] + b1 };
            *(float2*)&C[(size_t)row0 * Nt + col]       = v0;
            *(float2*)&C[(size_t)(row0 + 8) * Nt + col] = v1;
        }
    }
}

// ---------------------------------------------------------------------------
// Tensor-core flash attention (bf16x3, causal).
// Grid: (S/128, B*H). Block: 256 threads = 8 warps; warp w owns q rows w*16..+15.
// BN=64 keys per iteration. S = Qh.Kh + Ql.Kh + Qh.Kl ; O += Ph.Vh + Pl.Vh + Ph.Vl.
// SMEM rows padded: 128 bf16 -> 136 (272 B) for conflict-free ldmatrix.
// ---------------------------------------------------------------------------
#define FR_STR  272                       // bytes per smem row
#define OFF_QH  0
#define OFF_QL  (128 * FR_STR)            // 34816
#define OFF_KH  (2 * 128 * FR_STR)        // 69632
#define OFF_KL  (OFF_KH + 64 * FR_STR)    // 87040
#define OFF_VH  (OFF_KL + 64 * FR_STR)    // 104448
#define OFF_VL  (OFF_VH + 64 * FR_STR)    // 121856
#define FLASH_SMEM (OFF_VL + 64 * FR_STR) // 139264

__device__ __forceinline__ void split_store4(char* smc, int off_h, int off_l,
                                             int r, int c4, float4 v)
{
    __nv_bfloat16 hx = __float2bfloat16_rn(v.x);
    __nv_bfloat16 hy = __float2bfloat16_rn(v.y);
    __nv_bfloat16 hz = __float2bfloat16_rn(v.z);
    __nv_bfloat16 hw = __float2bfloat16_rn(v.w);
    __nv_bfloat16 lx = __float2bfloat16_rn(v.x - __bfloat162float(hx));
    __nv_bfloat16 ly = __float2bfloat16_rn(v.y - __bfloat162float(hy));
    __nv_bfloat16 lz = __float2bfloat16_rn(v.z - __bfloat162float(hz));
    __nv_bfloat16 lw = __float2bfloat16_rn(v.w - __bfloat162float(hw));
    uint32_t* ph = (uint32_t*)(smc + off_h + r * FR_STR + c4 * 2);
    uint32_t* pl = (uint32_t*)(smc + off_l + r * FR_STR + c4 * 2);
    ph[0] = pack_bf(hx, hy); ph[1] = pack_bf(hz, hw);
    pl[0] = pack_bf(lx, ly); pl[1] = pack_bf(lz, lw);
}

__global__ __launch_bounds__(256, 1) void flash_mma_kernel(
    const float* __restrict__ qkv, float* __restrict__ att)
{
    extern __shared__ char smc[];
    const uint32_t sb = smem_u32(smc);
    const int tid = threadIdx.x, w = tid >> 5, lane = tid & 31;
    const int b = blockIdx.y / NH, h = blockIdx.y % NH;
    const int qm0 = blockIdx.x << 7;
    const float scale = 0.08838834764831845f;   // 1/sqrt(128)

    // ---- Load + scale + split Q tile [128,128] ----
    const float* qg = qkv + (size_t)(b * S_LEN + qm0) * (3 * CDIM) + h * HD;
    for (int i = tid; i < 128 * 32; i += 256) {
        int r = i >> 5, c4 = (i & 31) << 2;
        float4 v = *(const float4*)(qg + (size_t)r * (3 * CDIM) + c4);
        v.x *= scale; v.y *= scale; v.z *= scale; v.w *= scale;
        split_store4(smc, OFF_QH, OFF_QL, r, c4, v);
    }

    float m_i[2] = { -1e30f, -1e30f }, l_i[2] = { 0.f, 0.f };
    float o[16][4];
#pragma unroll
    for (int n = 0; n < 16; n++)
#pragma unroll
        for (int r = 0; r < 4; r++) o[n][r] = 0.f;

    // ldmatrix lane addressing
    const int a_row = (w << 4) + (lane & 15);
    const int a_k8  = (lane >> 4) << 3;
    const int b_row = (lane & 7) + (((lane >> 3) >> 1) << 3);
    const int b_k8  = ((lane >> 3) & 1) << 3;
    const int v_row = lane & 15;
    const int v_n8  = (lane >> 4) << 3;

    const int row_t = qm0 + (w << 4) + (lane >> 2);   // this thread's top row
    const int col_q = (lane & 3) << 1;

    const int nkb = 2 * blockIdx.x + 2;
    for (int kb = 0; kb < nkb; kb++) {
        const float* kg = qkv + (size_t)(b * S_LEN + (kb << 6)) * (3 * CDIM) + CDIM + h * HD;
        const float* vg = kg + CDIM;
        __syncthreads();
        for (int i = tid; i < 64 * 32; i += 256) {
            int r = i >> 5, c4 = (i & 31) << 2;
            float4 kv = *(const float4*)(kg + (size_t)r * (3 * CDIM) + c4);
            split_store4(smc, OFF_KH, OFF_KL, r, c4, kv);
            float4 vv = *(const float4*)(vg + (size_t)r * (3 * CDIM) + c4);
            split_store4(smc, OFF_VH, OFF_VL, r, c4, vv);
        }
        __syncthreads();

        // ---- S = Q'K'^T (3-term bf16) ----
        float s[8][4];
#pragma unroll
        for (int n = 0; n < 8; n++)
#pragma unroll
            for (int r = 0; r < 4; r++) s[n][r] = 0.f;

#pragma unroll
        for (int kt = 0; kt < 8; kt++) {
            const uint32_t koff = (uint32_t)(kt * 16 + a_k8) * 2;
            uint32_t aH[4], aL[4];
            ldm_x4(sb + OFF_QH + (uint32_t)a_row * FR_STR + koff,
                   aH[0], aH[1], aH[2], aH[3]);
            ldm_x4(sb + OFF_QL + (uint32_t)a_row * FR_STR + koff,
                   aL[0], aL[1], aL[2], aL[3]);
            const uint32_t kboff = (uint32_t)(kt * 16 + b_k8) * 2;
#pragma unroll
            for (int nb = 0; nb < 4; nb++) {
                uint32_t h0, h1, h2, h3, u0, u1, u2, u3;
                ldm_x4(sb + OFF_KH + (uint32_t)(nb * 16 + b_row) * FR_STR + kboff,
                       h0, h1, h2, h3);
                ldm_x4(sb + OFF_KL + (uint32_t)(nb * 16 + b_row) * FR_STR + kboff,
                       u0, u1, u2, u3);
                uint32_t bh0[2] = { h0, h1 }, bh1[2] = { h2, h3 };
                uint32_t bl0[2] = { u0, u1 }, bl1[2] = { u2, u3 };
                mma16816(s[2 * nb],     aH, bh0);
                mma16816(s[2 * nb],     aL, bh0);
                mma16816(s[2 * nb],     aH, bl0);
                mma16816(s[2 * nb + 1], aH, bh1);
                mma16816(s[2 * nb + 1], aL, bh1);
                mma16816(s[2 * nb + 1], aH, bl1);
            }
        }

        // ---- causal mask (only near diagonal) ----
        if (kb >= 2 * blockIdx.x) {
            const int col0 = (kb << 6) + col_q;
#pragma unroll
            for (int n = 0; n < 8; n++) {
                const int c = col0 + n * 8;
                if (c     > row_t)     s[n][0] = -1e30f;
                if (c + 1 > row_t)     s[n][1] = -1e30f;
                if (c     > row_t + 8) s[n][2] = -1e30f;
                if (c + 1 > row_t + 8) s[n][3] = -1e30f;
            }
        }

        // ---- online softmax (fp32) ----
        float alpha[2];
#pragma unroll
        for (int hf = 0; hf < 2; hf++) {
            float mx = -1e30f;
#pragma unroll
            for (int n = 0; n < 8; n++)
                mx = fmaxf(mx, fmaxf(s[n][2 * hf], s[n][2 * hf + 1]));
            mx = fmaxf(mx, __shfl_xor_sync(0xffffffffu, mx, 1));
            mx = fmaxf(mx, __shfl_xor_sync(0xffffffffu, mx, 2));
            const float mnew = fmaxf(m_i[hf], mx);
            alpha[hf] = __expf(m_i[hf] - mnew);
            m_i[hf] = mnew;
            float rs = 0.f;
#pragma unroll
            for (int n = 0; n < 8; n++) {
                s[n][2 * hf]     = __expf(s[n][2 * hf]     - mnew);
                s[n][2 * hf + 1] = __expf(s[n][2 * hf + 1] - mnew);
                rs += s[n][2 * hf] + s[n][2 * hf + 1];
            }
            rs += __shfl_xor_sync(0xffffffffu, rs, 1);
            rs += __shfl_xor_sync(0xffffffffu, rs, 2);
            l_i[hf] = l_i[hf] * alpha[hf] + rs;
        }
#pragma unroll
        for (int n = 0; n < 16; n++) {
            o[n][0] *= alpha[0]; o[n][1] *= alpha[0];
            o[n][2] *= alpha[1]; o[n][3] *= alpha[1];
        }

        // ---- P -> bf16 hi/lo A-fragments (in-register remap) ----
        uint32_t aPh[4][4], aPl[4][4];
#pragma unroll
        for (int kt = 0; kt < 4; kt++) {
#pragma unroll
            for (int half = 0; half < 2; half++) {    // tiles 2kt, 2kt+1
                const int t = 2 * kt + half;
                __nv_bfloat16 h0 = __float2bfloat16_rn(s[t][0]);
                __nv_bfloat16 h1 = __float2bfloat16_rn(s[t][1]);
                __nv_bfloat16 h2 = __float2bfloat16_rn(s[t][2]);
                __nv_bfloat16 h3 = __float2bfloat16_rn(s[t][3]);
                __nv_bfloat16 l0 = __float2bfloat16_rn(s[t][0] - __bfloat162float(h0));
                __nv_bfloat16 l1 = __float2bfloat16_rn(s[t][1] - __bfloat162float(h1));
                __nv_bfloat16 l2 = __float2bfloat16_rn(s[t][2] - __bfloat162float(h2));
                __nv_bfloat16 l3 = __float2bfloat16_rn(s[t][3] - __bfloat162float(h3));
                aPh[kt][2 * half + 0] = pack_bf(h0, h1);
                aPh[kt][2 * half + 1] = pack_bf(h2, h3);
                aPl[kt][2 * half + 0] = pack_bf(l0, l1);
                aPl[kt][2 * half + 1] = pack_bf(l2, l3);
            }
        }

        // ---- O += P'V' (3-term bf16) ----
#pragma unroll
        for (int kt = 0; kt < 4; kt++) {
            const uint32_t vro = (uint32_t)(kt * 16 + v_row) * FR_STR;
#pragma unroll
            for (int nv = 0; nv < 8; nv++) {
                const uint32_t noff = (uint32_t)(nv * 16 + v_n8) * 2;
                uint32_t h0, h1, h2, h3, u0, u1, u2, u3;
                ldm_x4_t(sb + OFF_VH + vro + noff, h0, h1, h2, h3);
                ldm_x4_t(sb + OFF_VL + vro + noff, u0, u1, u2, u3);
                uint32_t bh0[2] = { h0, h1 }, bh1[2] = { h2, h3 };
                uint32_t bl0[2] = { u0, u1 }, bl1[2] = { u2, u3 };
                mma16816(o[2 * nv],     aPh[kt], bh0);
                mma16816(o[2 * nv],     aPl[kt], bh0);
                mma16816(o[2 * nv],     aPh[kt], bl0);
                mma16816(o[2 * nv + 1], aPh[kt], bh1);
                mma16816(o[2 * nv + 1], aPl[kt], bh1);
                mma16816(o[2 * nv + 1], aPh[kt], bl1);
            }
        }
    }

    // ---- epilogue ----
    const float inv0 = 1.f / l_i[0], inv1 = 1.f / l_i[1];
    float* ab = att + (size_t)(b * S_LEN) * CDIM + h * HD;
#pragma unroll
    for (int n = 0; n < 16; n++) {
        const int col = n * 8 + col_q;
        float2 v0 = { o[n][0] * inv0, o[n][1] * inv0 };
        float2 v1 = { o[n][2] * inv1, o[n][3] * inv1 };
        *(float2*)(ab + (size_t)row_t * CDIM + col)       = v0;
        *(float2*)(ab + (size_t)(row_t + 8) * CDIM + col) = v1;
    }
}

// ---------------------------------------------------------------------------
extern "C" void kernel_launch(void* const* d_in, const int* in_sizes, int n_in,
                              void* d_out, int out_size)
{
    const float* x      = (const float*)d_in[0];
    const float* w_attn = (const float*)d_in[1];
    const float* b_attn = (const float*)d_in[2];
    const float* w_proj = (const float*)d_in[3];
    const float* b_proj = (const float*)d_in[4];
    float* out = (float*)d_out;

    float *qkv_ptr = nullptr, *att_ptr = nullptr;
    __nv_bfloat16 *a1 = nullptr, *wt1 = nullptr, *wt2 = nullptr;
    cudaGetSymbolAddress((void**)&qkv_ptr, g_qkv);
    cudaGetSymbolAddress((void**)&att_ptr, g_att);
    cudaGetSymbolAddress((void**)&a1,  g_a1);
    cudaGetSymbolAddress((void**)&wt1, g_wt1);
    cudaGetSymbolAddress((void**)&wt2, g_wt2);

    cudaFuncSetAttribute(mma_gemm_kernel,
                         cudaFuncAttributeMaxDynamicSharedMemorySize, GEMM_SMEM);
    cudaFuncSetAttribute(flash_mma_kernel,
                         cudaFuncAttributeMaxDynamicSharedMemorySize, FLASH_SMEM);

    // --- Stage 1: QKV = x @ w_attn + b ---
    asplit_kernel<<<(MTOT * CDIM + 255) / 256, 256>>>(x, a1, MTOT * CDIM, CDIM);
    {
        dim3 gt(CDIM / 32, (3 * CDIM) / 32), bt(32, 8);
        wsplit_kernel<<<gt, bt>>>(w_attn, wt1, CDIM, 3 * CDIM);
    }
    {
        dim3 g(3 * CDIM / 128, MTOT / 128);
        mma_gemm_kernel<<<g, 256, GEMM_SMEM>>>(a1, wt1, b_attn, qkv_ptr, 3 * CDIM);
    }

    // --- Stage 2: causal flash attention (bf16x3 tensor cores) ---
    {
        dim3 g(S_LEN / 128, NB * NH);
        flash_mma_kernel<<<g, 256, FLASH_SMEM>>>(qkv_ptr, att_ptr);
    }

    // --- Stage 3: out = att @ w_proj + b ---
    asplit_kernel<<<(MTOT * CDIM + 255) / 256, 256>>>(att_ptr, a1, MTOT * CDIM, CDIM);
    {
        dim3 gt(CDIM / 32, CDIM / 32), bt(32, 8);
        wsplit_kernel<<<gt, bt>>>(w_proj, wt2, CDIM, CDIM);
    }
    {
        dim3 g(CDIM / 128, MTOT / 128);
        mma_gemm_kernel<<<g, 256, GEMM_SMEM>>>(a1, wt2, b_proj, out, CDIM);
    }
}

// round 6
// speedup vs baseline: 2.5000x; 1.1043x over previous
#include <cuda_runtime.h>
#include <cuda_bf16.h>
#include <cstdint>
#include <math.h>

#define S_LEN 2048
#define NB    4
#define NH    6
#define HD    128
#define CDIM  768
#define MTOT  (NB * S_LEN)        // 8192 rows
#define KP    (3 * CDIM)          // 2304 = split-K for bf16x3 GEMM
#define GCH   64                  // GEMM K-chunk (bf16 elems)
#define NCH   (KP / GCH)          // 36 chunks

// ---------------------------------------------------------------------------
// Scratch (device globals: allocation-free rule)
// ---------------------------------------------------------------------------
__device__ float g_qkv[(size_t)MTOT * 3 * CDIM];            // [8192, 2304] f32
__device__ __nv_bfloat16 g_a1 [(size_t)MTOT * KP];          // A split [8192, 2304]
__device__ __nv_bfloat16 g_wt1[(size_t)(3 * CDIM) * KP];    // W_attn^T split
__device__ __nv_bfloat16 g_wt2[(size_t)CDIM * KP];          // W_proj^T split

__device__ __forceinline__ uint32_t smem_u32(const void* p) {
    uint32_t a;
    asm("{ .reg .u64 t; cvta.to.shared.u64 t, %1; cvt.u32.u64 %0, t; }" : "=r"(a) : "l"(p));
    return a;
}
__device__ __forceinline__ void ldm_x4(uint32_t addr, uint32_t& r0, uint32_t& r1,
                                       uint32_t& r2, uint32_t& r3)
{
    asm volatile("ldmatrix.sync.aligned.m8n8.x4.shared.b16 {%0,%1,%2,%3}, [%4];"
                 : "=r"(r0), "=r"(r1), "=r"(r2), "=r"(r3) : "r"(addr));
}
__device__ __forceinline__ void ldm_x4_t(uint32_t addr, uint32_t& r0, uint32_t& r1,
                                         uint32_t& r2, uint32_t& r3)
{
    asm volatile("ldmatrix.sync.aligned.m8n8.x4.trans.shared.b16 {%0,%1,%2,%3}, [%4];"
                 : "=r"(r0), "=r"(r1), "=r"(r2), "=r"(r3) : "r"(addr));
}
__device__ __forceinline__ void mma16816(float* c, const uint32_t* a, const uint32_t* b)
{
    asm volatile(
        "mma.sync.aligned.m16n8k16.row.col.f32.bf16.bf16.f32 "
        "{%0,%1,%2,%3}, {%4,%5,%6,%7}, {%8,%9}, {%0,%1,%2,%3};"
        : "+f"(c[0]), "+f"(c[1]), "+f"(c[2]), "+f"(c[3])
        : "r"(a[0]), "r"(a[1]), "r"(a[2]), "r"(a[3]), "r"(b[0]), "r"(b[1]));
}
__device__ __forceinline__ uint32_t pack_bf(__nv_bfloat16 lo, __nv_bfloat16 hi) {
    __nv_bfloat162 t(lo, hi);
    return *(uint32_t*)&t;
}

// ---------------------------------------------------------------------------
// Split kernels. A' = [Ah|Al|Ah], B' = [Bh|Bh|Bl] => AhBh + AlBh + AhBl
// ---------------------------------------------------------------------------
__global__ void asplit_kernel(const float* __restrict__ src,
                              __nv_bfloat16* __restrict__ dst, int total, int K)
{
    int idx = blockIdx.x * blockDim.x + threadIdx.x;
    if (idx >= total) return;
    int m = idx / K, k = idx - m * K;
    float v = src[idx];
    __nv_bfloat16 h = __float2bfloat16_rn(v);
    __nv_bfloat16 l = __float2bfloat16_rn(v - __bfloat162float(h));
    __nv_bfloat16* d = dst + (size_t)m * (3 * K) + k;
    d[0]     = h;
    d[K]     = l;
    d[2 * K] = h;
}

__global__ void wsplit_kernel(const float* __restrict__ W,
                              __nv_bfloat16* __restrict__ Wt, int K, int N)
{
    __shared__ float t[32][33];
    int kb = blockIdx.x * 32, nb = blockIdx.y * 32;
    int tx = threadIdx.x, ty = threadIdx.y;    // block (32, 8)
    for (int i = ty; i < 32; i += 8)
        t[i][tx] = W[(size_t)(kb + i) * N + nb + tx];
    __syncthreads();
    for (int i = ty; i < 32; i += 8) {
        int n = nb + i, k = kb + tx;
        float v = t[tx][i];
        __nv_bfloat16 h = __float2bfloat16_rn(v);
        __nv_bfloat16 l = __float2bfloat16_rn(v - __bfloat162float(h));
        __nv_bfloat16* d = Wt + (size_t)n * (3 * K) + k;
        d[0]     = h;
        d[K]     = h;
        d[2 * K] = l;
    }
}

// ---------------------------------------------------------------------------
// bf16 mma.sync GEMM (unchanged — measured ~300 TF/s)
// ---------------------------------------------------------------------------
#define AST 72
#define STAGE_B  (128 * AST * 2)
#define GEMM_SMEM (4 * STAGE_B)

__device__ __forceinline__ void g_load_tile(uint32_t sm_tile,
                                            const __nv_bfloat16* g, int k0, int tid)
{
#pragma unroll
    for (int i = 0; i < 4; i++) {
        int s = i * 256 + tid;
        int r = s >> 3, cg = s & 7;
        uint32_t dst = sm_tile + r * 144 + cg * 16;
        const void* src = g + (size_t)r * KP + k0 + cg * 8;
        asm volatile("cp.async.cg.shared.global [%0], [%1], 16;" :: "r"(dst), "l"(src));
    }
}

__global__ __launch_bounds__(256, 2) void mma_gemm_kernel(
    const __nv_bfloat16* __restrict__ A1, const __nv_bfloat16* __restrict__ Bt,
    const float* __restrict__ bias, float* __restrict__ C, int Nt)
{
    extern __shared__ char smem[];
    const uint32_t sb = smem_u32(smem);
    const int tid = threadIdx.x, wid = tid >> 5, lane = tid & 31;
    const int m0 = blockIdx.y << 7, n0 = blockIdx.x << 7;
    const int wm = wid & 1, wn = wid >> 1;

    const uint32_t sA[2] = { sb,               sb + STAGE_B };
    const uint32_t sB[2] = { sb + 2 * STAGE_B, sb + 3 * STAGE_B };

    const __nv_bfloat16* Ag = A1 + (size_t)m0 * KP;
    const __nv_bfloat16* Bg = Bt + (size_t)n0 * KP;

    float acc[4][4][4];
#pragma unroll
    for (int i = 0; i < 4; i++)
#pragma unroll
        for (int j = 0; j < 4; j++)
#pragma unroll
            for (int r = 0; r < 4; r++) acc[i][j][r] = 0.f;

    const int a_row = (wm << 6) + (lane & 15);
    const int a_kof = (lane >> 4) << 3;
    const int b_row = (wn << 5) + (lane & 7) + (((lane >> 3) >> 1) << 3);
    const int b_kof = ((lane >> 3) & 1) << 3;

    g_load_tile(sA[0], Ag, 0, tid);
    g_load_tile(sB[0], Bg, 0, tid);
    asm volatile("cp.async.commit_group;" ::: "memory");

    for (int c = 0; c < NCH; c++) {
        const int cur = c & 1;
        if (c + 1 < NCH) {
            const int nb = (c + 1) & 1;
            g_load_tile(sA[nb], Ag, (c + 1) * GCH, tid);
            g_load_tile(sB[nb], Bg, (c + 1) * GCH, tid);
            asm volatile("cp.async.commit_group;" ::: "memory");
            asm volatile("cp.async.wait_group 1;" ::: "memory");
        } else {
            asm volatile("cp.async.wait_group 0;" ::: "memory");
        }
        __syncthreads();

#pragma unroll
        for (int ks = 0; ks < 4; ks++) {
            const int kbase = ks << 4;
            uint32_t a[4][4];
#pragma unroll
            for (int mi = 0; mi < 4; mi++) {
                uint32_t addr = sA[cur] + (uint32_t)(a_row + mi * 16) * 144
                              + (uint32_t)(kbase + a_kof) * 2;
                ldm_x4(addr, a[mi][0], a[mi][1], a[mi][2], a[mi][3]);
            }
            uint32_t b[4][2];
#pragma unroll
            for (int nb2 = 0; nb2 < 2; nb2++) {
                uint32_t addr = sB[cur] + (uint32_t)(b_row + nb2 * 16) * 144
                              + (uint32_t)(kbase + b_kof) * 2;
                uint32_t t0, t1, t2, t3;
                ldm_x4(addr, t0, t1, t2, t3);
                b[nb2 * 2 + 0][0] = t0; b[nb2 * 2 + 0][1] = t1;
                b[nb2 * 2 + 1][0] = t2; b[nb2 * 2 + 1][1] = t3;
            }
#pragma unroll
            for (int mi = 0; mi < 4; mi++)
#pragma unroll
                for (int ni = 0; ni < 4; ni++)
                    mma16816(acc[mi][ni], a[mi], b[ni]);
        }
        __syncthreads();
    }

    const int r_top = m0 + (wm << 6) + (lane >> 2);
    const int c_base = n0 + (wn << 5) + ((lane & 3) << 1);
#pragma unroll
    for (int mi = 0; mi < 4; mi++) {
#pragma unroll
        for (int ni = 0; ni < 4; ni++) {
            const int col = c_base + ni * 8;
            const float b0 = bias[col], b1 = bias[col + 1];
            const int row0 = r_top + mi * 16;
            float2 v0 = { acc[mi][ni][0] + b0, acc[mi][ni][1] + b1 };
            float2 v1 = { acc[mi][ni][2] + b0, acc[mi][ni][3] + b1 };
            *(float2*)&C[(size_t)row0 * Nt + col]       = v0;
            *(float2*)&C[(size_t)(row0 + 8) * Nt + col] = v1;
        }
    }
}

// ---------------------------------------------------------------------------
// Tensor-core flash attention (bf16x3, causal) with cp.async K/V staging.
// Grid: (S/128, B*H), heaviest CTAs first. 8 warps; warp w owns q rows w*16..+15.
// Output written DIRECTLY in bf16 hi/lo/hi split layout (feeds proj GEMM).
// ---------------------------------------------------------------------------
#define FR_STR  272                       // bytes per split smem row (136 bf16)
#define OFF_QH  0
#define OFF_QL  (128 * FR_STR)            // 34816
#define OFF_KH  (2 * 128 * FR_STR)        // 69632
#define OFF_KL  (OFF_KH + 64 * FR_STR)    // 87040
#define OFF_VH  (OFF_KL + 64 * FR_STR)    // 104448
#define OFF_VL  (OFF_VH + 64 * FR_STR)    // 121856
#define OFF_STGK (OFF_VL + 64 * FR_STR)   // 139264 (fp32 staging, 512B rows)
#define OFF_STGV (OFF_STGK + 64 * 512)    // 172032
#define FLASH_SMEM (OFF_STGV + 64 * 512)  // 204800

__device__ __forceinline__ void split_store4(char* smc, int off_h, int off_l,
                                             int r, int c4, float4 v)
{
    __nv_bfloat16 hx = __float2bfloat16_rn(v.x);
    __nv_bfloat16 hy = __float2bfloat16_rn(v.y);
    __nv_bfloat16 hz = __float2bfloat16_rn(v.z);
    __nv_bfloat16 hw = __float2bfloat16_rn(v.w);
    __nv_bfloat16 lx = __float2bfloat16_rn(v.x - __bfloat162float(hx));
    __nv_bfloat16 ly = __float2bfloat16_rn(v.y - __bfloat162float(hy));
    __nv_bfloat16 lz = __float2bfloat16_rn(v.z - __bfloat162float(hz));
    __nv_bfloat16 lw = __float2bfloat16_rn(v.w - __bfloat162float(hw));
    uint32_t* ph = (uint32_t*)(smc + off_h + r * FR_STR + c4 * 2);
    uint32_t* pl = (uint32_t*)(smc + off_l + r * FR_STR + c4 * 2);
    ph[0] = pack_bf(hx, hy); ph[1] = pack_bf(hz, hw);
    pl[0] = pack_bf(lx, ly); pl[1] = pack_bf(lz, lw);
}

__device__ __forceinline__ void stage_load_kv(uint32_t stgK, uint32_t stgV,
                                              const float* kg, const float* vg, int tid)
{
#pragma unroll
    for (int i = 0; i < 8; i++) {
        int s = i * 256 + tid;
        int r = s >> 5, c4 = (s & 31) << 2;
        const void* ks = kg + (size_t)r * (3 * CDIM) + c4;
        const void* vs = vg + (size_t)r * (3 * CDIM) + c4;
        asm volatile("cp.async.cg.shared.global [%0], [%1], 16;"
                     :: "r"(stgK + r * 512 + c4 * 4), "l"(ks));
        asm volatile("cp.async.cg.shared.global [%0], [%1], 16;"
                     :: "r"(stgV + r * 512 + c4 * 4), "l"(vs));
    }
    asm volatile("cp.async.commit_group;" ::: "memory");
}

__global__ __launch_bounds__(256, 1) void flash_mma_kernel(
    const float* __restrict__ qkv, __nv_bfloat16* __restrict__ a1out)
{
    extern __shared__ char smc[];
    const uint32_t sb = smem_u32(smc);
    const int tid = threadIdx.x, w = tid >> 5, lane = tid & 31;
    const int b = blockIdx.y / NH, h = blockIdx.y % NH;
    const int p = gridDim.x - 1 - blockIdx.x;     // heaviest first
    const int qm0 = p << 7;
    const float scale = 0.08838834764831845f;     // 1/sqrt(128)

    const uint32_t stgK = sb + OFF_STGK, stgV = sb + OFF_STGV;
    const float* kv0 = qkv + (size_t)(b * S_LEN) * (3 * CDIM) + h * HD;

    // prefetch K/V tile 0
    stage_load_kv(stgK, stgV, kv0 + CDIM, kv0 + 2 * CDIM, tid);

    // ---- Load + scale + split Q tile [128,128] ----
    const float* qg = kv0 + (size_t)qm0 * (3 * CDIM);
    for (int i = tid; i < 128 * 32; i += 256) {
        int r = i >> 5, c4 = (i & 31) << 2;
        float4 v = *(const float4*)(qg + (size_t)r * (3 * CDIM) + c4);
        v.x *= scale; v.y *= scale; v.z *= scale; v.w *= scale;
        split_store4(smc, OFF_QH, OFF_QL, r, c4, v);
    }

    float m_i[2] = { -1e30f, -1e30f }, l_i[2] = { 0.f, 0.f };
    float o[16][4];
#pragma unroll
    for (int n = 0; n < 16; n++)
#pragma unroll
        for (int r = 0; r < 4; r++) o[n][r] = 0.f;

    const int a_row = (w << 4) + (lane & 15);
    const int a_k8  = (lane >> 4) << 3;
    const int b_row = (lane & 7) + (((lane >> 3) >> 1) << 3);
    const int b_k8  = ((lane >> 3) & 1) << 3;
    const int v_row = lane & 15;
    const int v_n8  = (lane >> 4) << 3;

    const int row_t = qm0 + (w << 4) + (lane >> 2);
    const int col_q = (lane & 3) << 1;

    const int nkb = 2 * p + 2;
    for (int kb = 0; kb < nkb; kb++) {
        asm volatile("cp.async.wait_group 0;" ::: "memory");
        __syncthreads();   // staging visible; prev compute done with split bufs

        // ---- convert staging fp32 -> hi/lo split buffers ----
        const float* stK = (const float*)(smc + OFF_STGK);
        const float* stV = (const float*)(smc + OFF_STGV);
        for (int i = tid; i < 64 * 32; i += 256) {
            int r = i >> 5, c4 = (i & 31) << 2;
            float4 kvv = *(const float4*)(stK + r * 128 + c4);
            split_store4(smc, OFF_KH, OFF_KL, r, c4, kvv);
            float4 vvv = *(const float4*)(stV + r * 128 + c4);
            split_store4(smc, OFF_VH, OFF_VL, r, c4, vvv);
        }
        __syncthreads();   // split bufs ready; staging free

        if (kb + 1 < nkb) {
            const float* kg = kv0 + (size_t)((kb + 1) << 6) * (3 * CDIM) + CDIM;
            stage_load_kv(stgK, stgV, kg, kg + CDIM, tid);
        }

        // ---- S = Q'K'^T (3-term bf16) ----
        float s[8][4];
#pragma unroll
        for (int n = 0; n < 8; n++)
#pragma unroll
            for (int r = 0; r < 4; r++) s[n][r] = 0.f;

#pragma unroll
        for (int kt = 0; kt < 8; kt++) {
            const uint32_t koff = (uint32_t)(kt * 16 + a_k8) * 2;
            uint32_t aH[4], aL[4];
            ldm_x4(sb + OFF_QH + (uint32_t)a_row * FR_STR + koff,
                   aH[0], aH[1], aH[2], aH[3]);
            ldm_x4(sb + OFF_QL + (uint32_t)a_row * FR_STR + koff,
                   aL[0], aL[1], aL[2], aL[3]);
            const uint32_t kboff = (uint32_t)(kt * 16 + b_k8) * 2;
#pragma unroll
            for (int nb = 0; nb < 4; nb++) {
                uint32_t h0, h1, h2, h3, u0, u1, u2, u3;
                ldm_x4(sb + OFF_KH + (uint32_t)(nb * 16 + b_row) * FR_STR + kboff,
                       h0, h1, h2, h3);
                ldm_x4(sb + OFF_KL + (uint32_t)(nb * 16 + b_row) * FR_STR + kboff,
                       u0, u1, u2, u3);
                uint32_t bh0[2] = { h0, h1 }, bh1[2] = { h2, h3 };
                uint32_t bl0[2] = { u0, u1 }, bl1[2] = { u2, u3 };
                mma16816(s[2 * nb],     aH, bh0);
                mma16816(s[2 * nb],     aL, bh0);
                mma16816(s[2 * nb],     aH, bl0);
                mma16816(s[2 * nb + 1], aH, bh1);
                mma16816(s[2 * nb + 1], aL, bh1);
                mma16816(s[2 * nb + 1], aH, bl1);
            }
        }

        // ---- causal mask (only near diagonal) ----
        if (kb >= 2 * p) {
            const int col0 = (kb << 6) + col_q;
#pragma unroll
            for (int n = 0; n < 8; n++) {
                const int c = col0 + n * 8;
                if (c     > row_t)     s[n][0] = -1e30f;
                if (c + 1 > row_t)     s[n][1] = -1e30f;
                if (c     > row_t + 8) s[n][2] = -1e30f;
                if (c + 1 > row_t + 8) s[n][3] = -1e30f;
            }
        }

        // ---- online softmax (fp32) ----
        float alpha[2];
#pragma unroll
        for (int hf = 0; hf < 2; hf++) {
            float mx = -1e30f;
#pragma unroll
            for (int n = 0; n < 8; n++)
                mx = fmaxf(mx, fmaxf(s[n][2 * hf], s[n][2 * hf + 1]));
            mx = fmaxf(mx, __shfl_xor_sync(0xffffffffu, mx, 1));
            mx = fmaxf(mx, __shfl_xor_sync(0xffffffffu, mx, 2));
            const float mnew = fmaxf(m_i[hf], mx);
            alpha[hf] = __expf(m_i[hf] - mnew);
            m_i[hf] = mnew;
            float rs = 0.f;
#pragma unroll
            for (int n = 0; n < 8; n++) {
                s[n][2 * hf]     = __expf(s[n][2 * hf]     - mnew);
                s[n][2 * hf + 1] = __expf(s[n][2 * hf + 1] - mnew);
                rs += s[n][2 * hf] + s[n][2 * hf + 1];
            }
            rs += __shfl_xor_sync(0xffffffffu, rs, 1);
            rs += __shfl_xor_sync(0xffffffffu, rs, 2);
            l_i[hf] = l_i[hf] * alpha[hf] + rs;
        }
#pragma unroll
        for (int n = 0; n < 16; n++) {
            o[n][0] *= alpha[0]; o[n][1] *= alpha[0];
            o[n][2] *= alpha[1]; o[n][3] *= alpha[1];
        }

        // ---- P -> bf16 hi/lo A-fragments (in-register remap) ----
        uint32_t aPh[4][4], aPl[4][4];
#pragma unroll
        for (int kt = 0; kt < 4; kt++) {
#pragma unroll
            for (int half = 0; half < 2; half++) {
                const int t = 2 * kt + half;
                __nv_bfloat16 h0 = __float2bfloat16_rn(s[t][0]);
                __nv_bfloat16 h1 = __float2bfloat16_rn(s[t][1]);
                __nv_bfloat16 h2 = __float2bfloat16_rn(s[t][2]);
                __nv_bfloat16 h3 = __float2bfloat16_rn(s[t][3]);
                __nv_bfloat16 l0 = __float2bfloat16_rn(s[t][0] - __bfloat162float(h0));
                __nv_bfloat16 l1 = __float2bfloat16_rn(s[t][1] - __bfloat162float(h1));
                __nv_bfloat16 l2 = __float2bfloat16_rn(s[t][2] - __bfloat162float(h2));
                __nv_bfloat16 l3 = __float2bfloat16_rn(s[t][3] - __bfloat162float(h3));
                aPh[kt][2 * half + 0] = pack_bf(h0, h1);
                aPh[kt][2 * half + 1] = pack_bf(h2, h3);
                aPl[kt][2 * half + 0] = pack_bf(l0, l1);
                aPl[kt][2 * half + 1] = pack_bf(l2, l3);
            }
        }

        // ---- O += P'V' (3-term bf16) ----
#pragma unroll
        for (int kt = 0; kt < 4; kt++) {
            const uint32_t vro = (uint32_t)(kt * 16 + v_row) * FR_STR;
#pragma unroll
            for (int nv = 0; nv < 8; nv++) {
                const uint32_t noff = (uint32_t)(nv * 16 + v_n8) * 2;
                uint32_t h0, h1, h2, h3, u0, u1, u2, u3;
                ldm_x4_t(sb + OFF_VH + vro + noff, h0, h1, h2, h3);
                ldm_x4_t(sb + OFF_VL + vro + noff, u0, u1, u2, u3);
                uint32_t bh0[2] = { h0, h1 }, bh1[2] = { h2, h3 };
                uint32_t bl0[2] = { u0, u1 }, bl1[2] = { u2, u3 };
                mma16816(o[2 * nv],     aPh[kt], bh0);
                mma16816(o[2 * nv],     aPl[kt], bh0);
                mma16816(o[2 * nv],     aPh[kt], bl0);
                mma16816(o[2 * nv + 1], aPh[kt], bh1);
                mma16816(o[2 * nv + 1], aPl[kt], bh1);
                mma16816(o[2 * nv + 1], aPh[kt], bl1);
            }
        }
    }

    // ---- epilogue: write O directly in split [hi | lo | hi] layout ----
    const float inv0 = 1.f / l_i[0], inv1 = 1.f / l_i[1];
    __nv_bfloat16* ab = a1out + (size_t)(b * S_LEN) * KP + h * HD;
#pragma unroll
    for (int n = 0; n < 16; n++) {
        const int col = n * 8 + col_q;
        float v00 = o[n][0] * inv0, v01 = o[n][1] * inv0;
        float v10 = o[n][2] * inv1, v11 = o[n][3] * inv1;
        __nv_bfloat16 h00 = __float2bfloat16_rn(v00), h01 = __float2bfloat16_rn(v01);
        __nv_bfloat16 h10 = __float2bfloat16_rn(v10), h11 = __float2bfloat16_rn(v11);
        uint32_t hp0 = pack_bf(h00, h01), hp1 = pack_bf(h10, h11);
        uint32_t lp0 = pack_bf(__float2bfloat16_rn(v00 - __bfloat162float(h00)),
                               __float2bfloat16_rn(v01 - __bfloat162float(h01)));
        uint32_t lp1 = pack_bf(__float2bfloat16_rn(v10 - __bfloat162float(h10)),
                               __float2bfloat16_rn(v11 - __bfloat162float(h11)));
        __nv_bfloat16* p0 = ab + (size_t)row_t * KP + col;
        __nv_bfloat16* p1 = ab + (size_t)(row_t + 8) * KP + col;
        *(uint32_t*)(p0)            = hp0;
        *(uint32_t*)(p0 + CDIM)     = lp0;
        *(uint32_t*)(p0 + 2 * CDIM) = hp0;
        *(uint32_t*)(p1)            = hp1;
        *(uint32_t*)(p1 + CDIM)     = lp1;
        *(uint32_t*)(p1 + 2 * CDIM) = hp1;
    }
}

// ---------------------------------------------------------------------------
extern "C" void kernel_launch(void* const* d_in, const int* in_sizes, int n_in,
                              void* d_out, int out_size)
{
    const float* x      = (const float*)d_in[0];
    const float* w_attn = (const float*)d_in[1];
    const float* b_attn = (const float*)d_in[2];
    const float* w_proj = (const float*)d_in[3];
    const float* b_proj = (const float*)d_in[4];
    float* out = (float*)d_out;

    float *qkv_ptr = nullptr;
    __nv_bfloat16 *a1 = nullptr, *wt1 = nullptr, *wt2 = nullptr;
    cudaGetSymbolAddress((void**)&qkv_ptr, g_qkv);
    cudaGetSymbolAddress((void**)&a1,  g_a1);
    cudaGetSymbolAddress((void**)&wt1, g_wt1);
    cudaGetSymbolAddress((void**)&wt2, g_wt2);

    cudaFuncSetAttribute(mma_gemm_kernel,
                         cudaFuncAttributeMaxDynamicSharedMemorySize, GEMM_SMEM);
    cudaFuncSetAttribute(flash_mma_kernel,
                         cudaFuncAttributeMaxDynamicSharedMemorySize, FLASH_SMEM);

    // --- Stage 1: QKV = x @ w_attn + b ---
    asplit_kernel<<<(MTOT * CDIM + 255) / 256, 256>>>(x, a1, MTOT * CDIM, CDIM);
    {
        dim3 gt(CDIM / 32, (3 * CDIM) / 32), bt(32, 8);
        wsplit_kernel<<<gt, bt>>>(w_attn, wt1, CDIM, 3 * CDIM);
    }
    {
        dim3 g(3 * CDIM / 128, MTOT / 128);
        mma_gemm_kernel<<<g, 256, GEMM_SMEM>>>(a1, wt1, b_attn, qkv_ptr, 3 * CDIM);
    }

    // --- Stage 2: causal flash attention (bf16x3), writes split output ---
    {
        dim3 g(S_LEN / 128, NB * NH);
        flash_mma_kernel<<<g, 256, FLASH_SMEM>>>(qkv_ptr, a1);
    }

    // --- Stage 3: out = att @ w_proj + b (att already split in a1) ---
    {
        dim3 gt(CDIM / 32, CDIM / 32), bt(32, 8);
        wsplit_kernel<<<gt, bt>>>(w_proj, wt2, CDIM, CDIM);
    }
    {
        dim3 g(CDIM / 128, MTOT / 128);
        mma_gemm_kernel<<<g, 256, GEMM_SMEM>>>(a1, wt2, b_proj, out, CDIM);
    }
}

// round 7
// speedup vs baseline: 2.6992x; 1.0797x over previous
#include <cuda_runtime.h>
#include <cuda_bf16.h>
#include <cstdint>
#include <math.h>

#define S_LEN 2048
#define NB    4
#define NH    6
#define HD    128
#define CDIM  768
#define MTOT  (NB * S_LEN)        // 8192 rows
#define KP    (3 * CDIM)          // 2304 = split-K for bf16x3 GEMM
#define GCH   64                  // GEMM K-chunk (bf16 elems)
#define NCH   (KP / GCH)          // 36 chunks
#define QSCALE 0.08838834764831845f

// ---------------------------------------------------------------------------
// Scratch (device globals: allocation-free rule)
// ---------------------------------------------------------------------------
__device__ __nv_bfloat16 g_a1 [(size_t)MTOT * KP];          // A split [8192, 2304]
__device__ __nv_bfloat16 g_wt1[(size_t)(3 * CDIM) * KP];    // W_attn^T split
__device__ __nv_bfloat16 g_wt2[(size_t)CDIM * KP];          // W_proj^T split
__device__ __nv_bfloat16 g_qh [(size_t)MTOT * (3 * CDIM)];  // QKV hi plane
__device__ __nv_bfloat16 g_ql [(size_t)MTOT * (3 * CDIM)];  // QKV lo plane

__device__ __forceinline__ uint32_t smem_u32(const void* p) {
    uint32_t a;
    asm("{ .reg .u64 t; cvta.to.shared.u64 t, %1; cvt.u32.u64 %0, t; }" : "=r"(a) : "l"(p));
    return a;
}
__device__ __forceinline__ void ldm_x4(uint32_t addr, uint32_t& r0, uint32_t& r1,
                                       uint32_t& r2, uint32_t& r3)
{
    asm volatile("ldmatrix.sync.aligned.m8n8.x4.shared.b16 {%0,%1,%2,%3}, [%4];"
                 : "=r"(r0), "=r"(r1), "=r"(r2), "=r"(r3) : "r"(addr));
}
__device__ __forceinline__ void ldm_x4_t(uint32_t addr, uint32_t& r0, uint32_t& r1,
                                         uint32_t& r2, uint32_t& r3)
{
    asm volatile("ldmatrix.sync.aligned.m8n8.x4.trans.shared.b16 {%0,%1,%2,%3}, [%4];"
                 : "=r"(r0), "=r"(r1), "=r"(r2), "=r"(r3) : "r"(addr));
}
__device__ __forceinline__ void mma16816(float* c, const uint32_t* a, const uint32_t* b)
{
    asm volatile(
        "mma.sync.aligned.m16n8k16.row.col.f32.bf16.bf16.f32 "
        "{%0,%1,%2,%3}, {%4,%5,%6,%7}, {%8,%9}, {%0,%1,%2,%3};"
        : "+f"(c[0]), "+f"(c[1]), "+f"(c[2]), "+f"(c[3])
        : "r"(a[0]), "r"(a[1]), "r"(a[2]), "r"(a[3]), "r"(b[0]), "r"(b[1]));
}
__device__ __forceinline__ uint32_t pack_bf(__nv_bfloat16 lo, __nv_bfloat16 hi) {
    __nv_bfloat162 t(lo, hi);
    return *(uint32_t*)&t;
}

// ---------------------------------------------------------------------------
// Split kernels. A' = [Ah|Al|Ah], B' = [Bh|Bh|Bl] => AhBh + AlBh + AhBl
// ---------------------------------------------------------------------------
__global__ void asplit_kernel(const float* __restrict__ src,
                              __nv_bfloat16* __restrict__ dst, int total, int K)
{
    int idx = blockIdx.x * blockDim.x + threadIdx.x;
    if (idx >= total) return;
    int m = idx / K, k = idx - m * K;
    float v = src[idx];
    __nv_bfloat16 h = __float2bfloat16_rn(v);
    __nv_bfloat16 l = __float2bfloat16_rn(v - __bfloat162float(h));
    __nv_bfloat16* d = dst + (size_t)m * (3 * K) + k;
    d[0]     = h;
    d[K]     = l;
    d[2 * K] = h;
}

__global__ void wsplit_kernel(const float* __restrict__ W,
                              __nv_bfloat16* __restrict__ Wt, int K, int N)
{
    __shared__ float t[32][33];
    int kb = blockIdx.x * 32, nb = blockIdx.y * 32;
    int tx = threadIdx.x, ty = threadIdx.y;    // block (32, 8)
    for (int i = ty; i < 32; i += 8)
        t[i][tx] = W[(size_t)(kb + i) * N + nb + tx];
    __syncthreads();
    for (int i = ty; i < 32; i += 8) {
        int n = nb + i, k = kb + tx;
        float v = t[tx][i];
        __nv_bfloat16 h = __float2bfloat16_rn(v);
        __nv_bfloat16 l = __float2bfloat16_rn(v - __bfloat162float(h));
        __nv_bfloat16* d = Wt + (size_t)n * (3 * K) + k;
        d[0]     = h;
        d[K]     = h;
        d[2 * K] = l;
    }
}

// ---------------------------------------------------------------------------
// bf16 mma.sync GEMM.
// mode 0: C = f32 out (+bias).   mode 1: write hi/lo bf16 planes (+bias),
//         with Q columns (col < CDIM) pre-scaled by 1/sqrt(D) in f32.
// ---------------------------------------------------------------------------
#define AST 72
#define STAGE_B  (128 * AST * 2)
#define GEMM_SMEM (4 * STAGE_B)

__device__ __forceinline__ void g_load_tile(uint32_t sm_tile,
                                            const __nv_bfloat16* g, int k0, int tid)
{
#pragma unroll
    for (int i = 0; i < 4; i++) {
        int s = i * 256 + tid;
        int r = s >> 3, cg = s & 7;
        uint32_t dst = sm_tile + r * 144 + cg * 16;
        const void* src = g + (size_t)r * KP + k0 + cg * 8;
        asm volatile("cp.async.cg.shared.global [%0], [%1], 16;" :: "r"(dst), "l"(src));
    }
}

__global__ __launch_bounds__(256, 2) void mma_gemm_kernel(
    const __nv_bfloat16* __restrict__ A1, const __nv_bfloat16* __restrict__ Bt,
    const float* __restrict__ bias, float* __restrict__ C,
    __nv_bfloat16* __restrict__ hiP, __nv_bfloat16* __restrict__ loP,
    int Nt, int mode)
{
    extern __shared__ char smem[];
    const uint32_t sb = smem_u32(smem);
    const int tid = threadIdx.x, wid = tid >> 5, lane = tid & 31;
    const int m0 = blockIdx.y << 7, n0 = blockIdx.x << 7;
    const int wm = wid & 1, wn = wid >> 1;

    const uint32_t sA[2] = { sb,               sb + STAGE_B };
    const uint32_t sB[2] = { sb + 2 * STAGE_B, sb + 3 * STAGE_B };

    const __nv_bfloat16* Ag = A1 + (size_t)m0 * KP;
    const __nv_bfloat16* Bg = Bt + (size_t)n0 * KP;

    float acc[4][4][4];
#pragma unroll
    for (int i = 0; i < 4; i++)
#pragma unroll
        for (int j = 0; j < 4; j++)
#pragma unroll
            for (int r = 0; r < 4; r++) acc[i][j][r] = 0.f;

    const int a_row = (wm << 6) + (lane & 15);
    const int a_kof = (lane >> 4) << 3;
    const int b_row = (wn << 5) + (lane & 7) + (((lane >> 3) >> 1) << 3);
    const int b_kof = ((lane >> 3) & 1) << 3;

    g_load_tile(sA[0], Ag, 0, tid);
    g_load_tile(sB[0], Bg, 0, tid);
    asm volatile("cp.async.commit_group;" ::: "memory");

    for (int c = 0; c < NCH; c++) {
        const int cur = c & 1;
        if (c + 1 < NCH) {
            const int nb = (c + 1) & 1;
            g_load_tile(sA[nb], Ag, (c + 1) * GCH, tid);
            g_load_tile(sB[nb], Bg, (c + 1) * GCH, tid);
            asm volatile("cp.async.commit_group;" ::: "memory");
            asm volatile("cp.async.wait_group 1;" ::: "memory");
        } else {
            asm volatile("cp.async.wait_group 0;" ::: "memory");
        }
        __syncthreads();

#pragma unroll
        for (int ks = 0; ks < 4; ks++) {
            const int kbase = ks << 4;
            uint32_t a[4][4];
#pragma unroll
            for (int mi = 0; mi < 4; mi++) {
                uint32_t addr = sA[cur] + (uint32_t)(a_row + mi * 16) * 144
                              + (uint32_t)(kbase + a_kof) * 2;
                ldm_x4(addr, a[mi][0], a[mi][1], a[mi][2], a[mi][3]);
            }
            uint32_t b[4][2];
#pragma unroll
            for (int nb2 = 0; nb2 < 2; nb2++) {
                uint32_t addr = sB[cur] + (uint32_t)(b_row + nb2 * 16) * 144
                              + (uint32_t)(kbase + b_kof) * 2;
                uint32_t t0, t1, t2, t3;
                ldm_x4(addr, t0, t1, t2, t3);
                b[nb2 * 2 + 0][0] = t0; b[nb2 * 2 + 0][1] = t1;
                b[nb2 * 2 + 1][0] = t2; b[nb2 * 2 + 1][1] = t3;
            }
#pragma unroll
            for (int mi = 0; mi < 4; mi++)
#pragma unroll
                for (int ni = 0; ni < 4; ni++)
                    mma16816(acc[mi][ni], a[mi], b[ni]);
        }
        __syncthreads();
    }

    const int r_top = m0 + (wm << 6) + (lane >> 2);
    const int c_base = n0 + (wn << 5) + ((lane & 3) << 1);
#pragma unroll
    for (int mi = 0; mi < 4; mi++) {
#pragma unroll
        for (int ni = 0; ni < 4; ni++) {
            const int col = c_base + ni * 8;
            const float b0 = bias[col], b1 = bias[col + 1];
            const int row0 = r_top + mi * 16;
            float v00 = acc[mi][ni][0] + b0, v01 = acc[mi][ni][1] + b1;
            float v10 = acc[mi][ni][2] + b0, v11 = acc[mi][ni][3] + b1;
            if (mode == 0) {
                float2 a0 = { v00, v01 }, a1v = { v10, v11 };
                *(float2*)&C[(size_t)row0 * Nt + col]       = a0;
                *(float2*)&C[(size_t)(row0 + 8) * Nt + col] = a1v;
            } else {
                if (col < CDIM) { v00 *= QSCALE; v01 *= QSCALE; v10 *= QSCALE; v11 *= QSCALE; }
                __nv_bfloat16 h00 = __float2bfloat16_rn(v00), h01 = __float2bfloat16_rn(v01);
                __nv_bfloat16 h10 = __float2bfloat16_rn(v10), h11 = __float2bfloat16_rn(v11);
                uint32_t hp0 = pack_bf(h00, h01), hp1 = pack_bf(h10, h11);
                uint32_t lp0 = pack_bf(__float2bfloat16_rn(v00 - __bfloat162float(h00)),
                                       __float2bfloat16_rn(v01 - __bfloat162float(h01)));
                uint32_t lp1 = pack_bf(__float2bfloat16_rn(v10 - __bfloat162float(h10)),
                                       __float2bfloat16_rn(v11 - __bfloat162float(h11)));
                *(uint32_t*)&hiP[(size_t)row0 * Nt + col]       = hp0;
                *(uint32_t*)&loP[(size_t)row0 * Nt + col]       = lp0;
                *(uint32_t*)&hiP[(size_t)(row0 + 8) * Nt + col] = hp1;
                *(uint32_t*)&loP[(size_t)(row0 + 8) * Nt + col] = lp1;
            }
        }
    }
}

// ---------------------------------------------------------------------------
// Tensor-core flash attention (bf16x3, causal). Pre-split hi/lo QKV planes,
// cp.async double-buffered K/V, no in-kernel conversion.
// Grid: (S/128, B*H) heaviest-first. 8 warps; warp w owns q rows w*16..+15.
// Output written directly in bf16 [hi | lo | hi] split layout for proj GEMM.
// ---------------------------------------------------------------------------
#define FR_STR  272                        // bytes per smem row (136 bf16)
#define OFF_QH  0
#define OFF_QL  (128 * FR_STR)             // 34816
#define KV_STAGE (4 * 64 * FR_STR)         // 69632 per stage (KH,KL,VH,VL)
#define OFF_KV0 (2 * 128 * FR_STR)         // 69632
#define SOFF_KH 0
#define SOFF_KL (64 * FR_STR)
#define SOFF_VH (2 * 64 * FR_STR)
#define SOFF_VL (3 * 64 * FR_STR)
#define FLASH_SMEM (OFF_KV0 + 2 * KV_STAGE)  // 208896

// one 64x128 bf16 plane tile: 64 rows x 16 chunks of 16B; 4 chunks/thread
__device__ __forceinline__ void stage_plane64(uint32_t dst,
                                              const __nv_bfloat16* src, int tid)
{
#pragma unroll
    for (int i = 0; i < 4; i++) {
        int s = i * 256 + tid;
        int r = s >> 4, c = s & 15;
        asm volatile("cp.async.cg.shared.global [%0], [%1], 16;"
                     :: "r"(dst + r * FR_STR + c * 16),
                        "l"(src + (size_t)r * (3 * CDIM) + c * 8));
    }
}

__global__ __launch_bounds__(256, 1) void flash_mma_kernel(
    const __nv_bfloat16* __restrict__ qh, const __nv_bfloat16* __restrict__ ql,
    __nv_bfloat16* __restrict__ a1out)
{
    extern __shared__ char smc[];
    const uint32_t sb = smem_u32(smc);
    const int tid = threadIdx.x, w = tid >> 5, lane = tid & 31;
    const int b = blockIdx.y / NH, h = blockIdx.y % NH;
    const int p = gridDim.x - 1 - blockIdx.x;     // heaviest first
    const int qm0 = p << 7;

    const __nv_bfloat16* qhB = qh + (size_t)(b * S_LEN) * (3 * CDIM) + h * HD;
    const __nv_bfloat16* qlB = ql + (size_t)(b * S_LEN) * (3 * CDIM) + h * HD;
    const int nkb = 2 * p + 2;

    // group 0: Q tiles (hi+lo, 128 rows) + KV stage 0
    {
        const __nv_bfloat16* qsrc_h = qhB + (size_t)qm0 * (3 * CDIM);
        const __nv_bfloat16* qsrc_l = qlB + (size_t)qm0 * (3 * CDIM);
#pragma unroll
        for (int i = 0; i < 8; i++) {
            int s = i * 256 + tid;
            int r = s >> 4, c = s & 15;
            asm volatile("cp.async.cg.shared.global [%0], [%1], 16;"
                         :: "r"(sb + OFF_QH + r * FR_STR + c * 16),
                            "l"(qsrc_h + (size_t)r * (3 * CDIM) + c * 8));
            asm volatile("cp.async.cg.shared.global [%0], [%1], 16;"
                         :: "r"(sb + OFF_QL + r * FR_STR + c * 16),
                            "l"(qsrc_l + (size_t)r * (3 * CDIM) + c * 8));
        }
        const uint32_t st0 = sb + OFF_KV0;
        stage_plane64(st0 + SOFF_KH, qhB + CDIM, tid);
        stage_plane64(st0 + SOFF_KL, qlB + CDIM, tid);
        stage_plane64(st0 + SOFF_VH, qhB + 2 * CDIM, tid);
        stage_plane64(st0 + SOFF_VL, qlB + 2 * CDIM, tid);
        asm volatile("cp.async.commit_group;" ::: "memory");
    }

    float m_i[2] = { -1e30f, -1e30f }, l_i[2] = { 0.f, 0.f };
    float o[16][4];
#pragma unroll
    for (int n = 0; n < 16; n++)
#pragma unroll
        for (int r = 0; r < 4; r++) o[n][r] = 0.f;

    const int a_row = (w << 4) + (lane & 15);
    const int a_k8  = (lane >> 4) << 3;
    const int b_row = (lane & 7) + (((lane >> 3) >> 1) << 3);
    const int b_k8  = ((lane >> 3) & 1) << 3;
    const int v_row = lane & 15;
    const int v_n8  = (lane >> 4) << 3;

    const int row_t = qm0 + (w << 4) + (lane >> 2);
    const int col_q = (lane & 3) << 1;

    for (int kb = 0; kb < nkb; kb++) {
        if (kb + 1 < nkb) {
            const uint32_t stn = sb + OFF_KV0 + ((kb + 1) & 1) * KV_STAGE;
            const size_t roff = (size_t)((kb + 1) << 6) * (3 * CDIM);
            stage_plane64(stn + SOFF_KH, qhB + roff + CDIM, tid);
            stage_plane64(stn + SOFF_KL, qlB + roff + CDIM, tid);
            stage_plane64(stn + SOFF_VH, qhB + roff + 2 * CDIM, tid);
            stage_plane64(stn + SOFF_VL, qlB + roff + 2 * CDIM, tid);
            asm volatile("cp.async.commit_group;" ::: "memory");
            asm volatile("cp.async.wait_group 1;" ::: "memory");
        } else {
            asm volatile("cp.async.wait_group 0;" ::: "memory");
        }
        __syncthreads();
        const uint32_t st = sb + OFF_KV0 + (kb & 1) * KV_STAGE;

        // ---- S = Q'K'^T (3-term bf16) ----
        float s[8][4];
#pragma unroll
        for (int n = 0; n < 8; n++)
#pragma unroll
            for (int r = 0; r < 4; r++) s[n][r] = 0.f;

#pragma unroll
        for (int kt = 0; kt < 8; kt++) {
            const uint32_t koff = (uint32_t)(kt * 16 + a_k8) * 2;
            uint32_t aH[4], aL[4];
            ldm_x4(sb + OFF_QH + (uint32_t)a_row * FR_STR + koff,
                   aH[0], aH[1], aH[2], aH[3]);
            ldm_x4(sb + OFF_QL + (uint32_t)a_row * FR_STR + koff,
                   aL[0], aL[1], aL[2], aL[3]);
            const uint32_t kboff = (uint32_t)(kt * 16 + b_k8) * 2;
#pragma unroll
            for (int nb = 0; nb < 4; nb++) {
                uint32_t h0, h1, h2, h3, u0, u1, u2, u3;
                ldm_x4(st + SOFF_KH + (uint32_t)(nb * 16 + b_row) * FR_STR + kboff,
                       h0, h1, h2, h3);
                ldm_x4(st + SOFF_KL + (uint32_t)(nb * 16 + b_row) * FR_STR + kboff,
                       u0, u1, u2, u3);
                uint32_t bh0[2] = { h0, h1 }, bh1[2] = { h2, h3 };
                uint32_t bl0[2] = { u0, u1 }, bl1[2] = { u2, u3 };
                mma16816(s[2 * nb],     aH, bh0);
                mma16816(s[2 * nb],     aL, bh0);
                mma16816(s[2 * nb],     aH, bl0);
                mma16816(s[2 * nb + 1], aH, bh1);
                mma16816(s[2 * nb + 1], aL, bh1);
                mma16816(s[2 * nb + 1], aH, bl1);
            }
        }

        // ---- causal mask (only near diagonal) ----
        if (kb >= 2 * p) {
            const int col0 = (kb << 6) + col_q;
#pragma unroll
            for (int n = 0; n < 8; n++) {
                const int c = col0 + n * 8;
                if (c     > row_t)     s[n][0] = -1e30f;
                if (c + 1 > row_t)     s[n][1] = -1e30f;
                if (c     > row_t + 8) s[n][2] = -1e30f;
                if (c + 1 > row_t + 8) s[n][3] = -1e30f;
            }
        }

        // ---- online softmax (fp32) ----
        float alpha[2];
#pragma unroll
        for (int hf = 0; hf < 2; hf++) {
            float mx = -1e30f;
#pragma unroll
            for (int n = 0; n < 8; n++)
                mx = fmaxf(mx, fmaxf(s[n][2 * hf], s[n][2 * hf + 1]));
            mx = fmaxf(mx, __shfl_xor_sync(0xffffffffu, mx, 1));
            mx = fmaxf(mx, __shfl_xor_sync(0xffffffffu, mx, 2));
            const float mnew = fmaxf(m_i[hf], mx);
            alpha[hf] = __expf(m_i[hf] - mnew);
            m_i[hf] = mnew;
            float rs = 0.f;
#pragma unroll
            for (int n = 0; n < 8; n++) {
                s[n][2 * hf]     = __expf(s[n][2 * hf]     - mnew);
                s[n][2 * hf + 1] = __expf(s[n][2 * hf + 1] - mnew);
                rs += s[n][2 * hf] + s[n][2 * hf + 1];
            }
            rs += __shfl_xor_sync(0xffffffffu, rs, 1);
            rs += __shfl_xor_sync(0xffffffffu, rs, 2);
            l_i[hf] = l_i[hf] * alpha[hf] + rs;
        }
#pragma unroll
        for (int n = 0; n < 16; n++) {
            o[n][0] *= alpha[0]; o[n][1] *= alpha[0];
            o[n][2] *= alpha[1]; o[n][3] *= alpha[1];
        }

        // ---- P -> bf16 hi/lo A-fragments ----
        uint32_t aPh[4][4], aPl[4][4];
#pragma unroll
        for (int kt = 0; kt < 4; kt++) {
#pragma unroll
            for (int half = 0; half < 2; half++) {
                const int t = 2 * kt + half;
                __nv_bfloat16 h0 = __float2bfloat16_rn(s[t][0]);
                __nv_bfloat16 h1 = __float2bfloat16_rn(s[t][1]);
                __nv_bfloat16 h2 = __float2bfloat16_rn(s[t][2]);
                __nv_bfloat16 h3 = __float2bfloat16_rn(s[t][3]);
                __nv_bfloat16 l0 = __float2bfloat16_rn(s[t][0] - __bfloat162float(h0));
                __nv_bfloat16 l1 = __float2bfloat16_rn(s[t][1] - __bfloat162float(h1));
                __nv_bfloat16 l2 = __float2bfloat16_rn(s[t][2] - __bfloat162float(h2));
                __nv_bfloat16 l3 = __float2bfloat16_rn(s[t][3] - __bfloat162float(h3));
                aPh[kt][2 * half + 0] = pack_bf(h0, h1);
                aPh[kt][2 * half + 1] = pack_bf(h2, h3);
                aPl[kt][2 * half + 0] = pack_bf(l0, l1);
                aPl[kt][2 * half + 1] = pack_bf(l2, l3);
            }
        }

        // ---- O += P'V' (3-term bf16) ----
#pragma unroll
        for (int kt = 0; kt < 4; kt++) {
            const uint32_t vro = (uint32_t)(kt * 16 + v_row) * FR_STR;
#pragma unroll
            for (int nv = 0; nv < 8; nv++) {
                const uint32_t noff = (uint32_t)(nv * 16 + v_n8) * 2;
                uint32_t h0, h1, h2, h3, u0, u1, u2, u3;
                ldm_x4_t(st + SOFF_VH + vro + noff, h0, h1, h2, h3);
                ldm_x4_t(st + SOFF_VL + vro + noff, u0, u1, u2, u3);
                uint32_t bh0[2] = { h0, h1 }, bh1[2] = { h2, h3 };
                uint32_t bl0[2] = { u0, u1 }, bl1[2] = { u2, u3 };
                mma16816(o[2 * nv],     aPh[kt], bh0);
                mma16816(o[2 * nv],     aPl[kt], bh0);
                mma16816(o[2 * nv],     aPh[kt], bl0);
                mma16816(o[2 * nv + 1], aPh[kt], bh1);
                mma16816(o[2 * nv + 1], aPl[kt], bh1);
                mma16816(o[2 * nv + 1], aPh[kt], bl1);
            }
        }
        __syncthreads();   // compute done before next iter overwrites stage
    }

    // ---- epilogue: write O directly in split [hi | lo | hi] layout ----
    const float inv0 = 1.f / l_i[0], inv1 = 1.f / l_i[1];
    __nv_bfloat16* ab = a1out + (size_t)(b * S_LEN) * KP + h * HD;
#pragma unroll
    for (int n = 0; n < 16; n++) {
        const int col = n * 8 + col_q;
        float v00 = o[n][0] * inv0, v01 = o[n][1] * inv0;
        float v10 = o[n][2] * inv1, v11 = o[n][3] * inv1;
        __nv_bfloat16 h00 = __float2bfloat16_rn(v00), h01 = __float2bfloat16_rn(v01);
        __nv_bfloat16 h10 = __float2bfloat16_rn(v10), h11 = __float2bfloat16_rn(v11);
        uint32_t hp0 = pack_bf(h00, h01), hp1 = pack_bf(h10, h11);
        uint32_t lp0 = pack_bf(__float2bfloat16_rn(v00 - __bfloat162float(h00)),
                               __float2bfloat16_rn(v01 - __bfloat162float(h01)));
        uint32_t lp1 = pack_bf(__float2bfloat16_rn(v10 - __bfloat162float(h10)),
                               __float2bfloat16_rn(v11 - __bfloat162float(h11)));
        __nv_bfloat16* p0 = ab + (size_t)row_t * KP + col;
        __nv_bfloat16* p1 = ab + (size_t)(row_t + 8) * KP + col;
        *(uint32_t*)(p0)            = hp0;
        *(uint32_t*)(p0 + CDIM)     = lp0;
        *(uint32_t*)(p0 + 2 * CDIM) = hp0;
        *(uint32_t*)(p1)            = hp1;
        *(uint32_t*)(p1 + CDIM)     = lp1;
        *(uint32_t*)(p1 + 2 * CDIM) = hp1;
    }
}

// ---------------------------------------------------------------------------
extern "C" void kernel_launch(void* const* d_in, const int* in_sizes, int n_in,
                              void* d_out, int out_size)
{
    const float* x      = (const float*)d_in[0];
    const float* w_attn = (const float*)d_in[1];
    const float* b_attn = (const float*)d_in[2];
    const float* w_proj = (const float*)d_in[3];
    const float* b_proj = (const float*)d_in[4];
    float* out = (float*)d_out;

    __nv_bfloat16 *a1 = nullptr, *wt1 = nullptr, *wt2 = nullptr, *qh = nullptr, *ql = nullptr;
    cudaGetSymbolAddress((void**)&a1,  g_a1);
    cudaGetSymbolAddress((void**)&wt1, g_wt1);
    cudaGetSymbolAddress((void**)&wt2, g_wt2);
    cudaGetSymbolAddress((void**)&qh,  g_qh);
    cudaGetSymbolAddress((void**)&ql,  g_ql);

    cudaFuncSetAttribute(mma_gemm_kernel,
                         cudaFuncAttributeMaxDynamicSharedMemorySize, GEMM_SMEM);
    cudaFuncSetAttribute(flash_mma_kernel,
                         cudaFuncAttributeMaxDynamicSharedMemorySize, FLASH_SMEM);

    // --- Stage 1: QKV = x @ w_attn + b -> hi/lo planes (Q pre-scaled) ---
    asplit_kernel<<<(MTOT * CDIM + 255) / 256, 256>>>(x, a1, MTOT * CDIM, CDIM);
    {
        dim3 gt(CDIM / 32, (3 * CDIM) / 32), bt(32, 8);
        wsplit_kernel<<<gt, bt>>>(w_attn, wt1, CDIM, 3 * CDIM);
    }
    {
        dim3 g(3 * CDIM / 128, MTOT / 128);
        mma_gemm_kernel<<<g, 256, GEMM_SMEM>>>(a1, wt1, b_attn, nullptr,
                                               qh, ql, 3 * CDIM, 1);
    }

    // --- Stage 2: causal flash attention (bf16x3), split planes in/out ---
    {
        dim3 g(S_LEN / 128, NB * NH);
        flash_mma_kernel<<<g, 256, FLASH_SMEM>>>(qh, ql, a1);
    }

    // --- Stage 3: out = att @ w_proj + b (att already split in a1) ---
    {
        dim3 gt(CDIM / 32, CDIM / 32), bt(32, 8);
        wsplit_kernel<<<gt, bt>>>(w_proj, wt2, CDIM, CDIM);
    }
    {
        dim3 g(CDIM / 128, MTOT / 128);
        mma_gemm_kernel<<<g, 256, GEMM_SMEM>>>(a1, wt2, b_proj, out,
                                               nullptr, nullptr, CDIM, 0);
    }
}

// round 8
// speedup vs baseline: 2.8913x; 1.0712x over previous
#include <cuda_runtime.h>
#include <cuda_bf16.h>
#include <cstdint>
#include <math.h>

#define S_LEN 2048
#define NB    4
#define NH    6
#define HD    128
#define CDIM  768
#define MTOT  (NB * S_LEN)        // 8192 rows
#define KP    (3 * CDIM)          // 2304 = split-K for bf16x3 GEMM
#define GCH   64                  // GEMM K-chunk (bf16 elems)
#define NCH   (KP / GCH)          // 36 chunks
#define QSCALE 0.08838834764831845f

// ---------------------------------------------------------------------------
// Scratch (device globals: allocation-free rule)
// ---------------------------------------------------------------------------
__device__ __nv_bfloat16 g_a1 [(size_t)MTOT * KP];          // A split [8192, 2304]
__device__ __nv_bfloat16 g_wt1[(size_t)(3 * CDIM) * KP];    // W_attn^T split
__device__ __nv_bfloat16 g_wt2[(size_t)CDIM * KP];          // W_proj^T split
__device__ __nv_bfloat16 g_qh [(size_t)MTOT * (3 * CDIM)];  // QKV hi plane
__device__ __nv_bfloat16 g_ql [(size_t)MTOT * (3 * CDIM)];  // QKV lo plane

__device__ __forceinline__ uint32_t smem_u32(const void* p) {
    uint32_t a;
    asm("{ .reg .u64 t; cvta.to.shared.u64 t, %1; cvt.u32.u64 %0, t; }" : "=r"(a) : "l"(p));
    return a;
}
__device__ __forceinline__ void ldm_x4(uint32_t addr, uint32_t& r0, uint32_t& r1,
                                       uint32_t& r2, uint32_t& r3)
{
    asm volatile("ldmatrix.sync.aligned.m8n8.x4.shared.b16 {%0,%1,%2,%3}, [%4];"
                 : "=r"(r0), "=r"(r1), "=r"(r2), "=r"(r3) : "r"(addr));
}
__device__ __forceinline__ void ldm_x4_t(uint32_t addr, uint32_t& r0, uint32_t& r1,
                                         uint32_t& r2, uint32_t& r3)
{
    asm volatile("ldmatrix.sync.aligned.m8n8.x4.trans.shared.b16 {%0,%1,%2,%3}, [%4];"
                 : "=r"(r0), "=r"(r1), "=r"(r2), "=r"(r3) : "r"(addr));
}
__device__ __forceinline__ void mma16816(float* c, const uint32_t* a, const uint32_t* b)
{
    asm volatile(
        "mma.sync.aligned.m16n8k16.row.col.f32.bf16.bf16.f32 "
        "{%0,%1,%2,%3}, {%4,%5,%6,%7}, {%8,%9}, {%0,%1,%2,%3};"
        : "+f"(c[0]), "+f"(c[1]), "+f"(c[2]), "+f"(c[3])
        : "r"(a[0]), "r"(a[1]), "r"(a[2]), "r"(a[3]), "r"(b[0]), "r"(b[1]));
}
__device__ __forceinline__ uint32_t pack_bf(__nv_bfloat16 lo, __nv_bfloat16 hi) {
    __nv_bfloat162 t(lo, hi);
    return *(uint32_t*)&t;
}

// ---------------------------------------------------------------------------
// Split kernels. A' = [Ah|Al|Ah], B' = [Bh|Bh|Bl] => AhBh + AlBh + AhBl
// ---------------------------------------------------------------------------
__global__ void asplit_kernel(const float* __restrict__ src,
                              __nv_bfloat16* __restrict__ dst, int total, int K)
{
    int idx = blockIdx.x * blockDim.x + threadIdx.x;
    if (idx >= total) return;
    int m = idx / K, k = idx - m * K;
    float v = src[idx];
    __nv_bfloat16 h = __float2bfloat16_rn(v);
    __nv_bfloat16 l = __float2bfloat16_rn(v - __bfloat162float(h));
    __nv_bfloat16* d = dst + (size_t)m * (3 * K) + k;
    d[0]     = h;
    d[K]     = l;
    d[2 * K] = h;
}

__global__ void wsplit_kernel(const float* __restrict__ W,
                              __nv_bfloat16* __restrict__ Wt, int K, int N)
{
    __shared__ float t[32][33];
    int kb = blockIdx.x * 32, nb = blockIdx.y * 32;
    int tx = threadIdx.x, ty = threadIdx.y;    // block (32, 8)
    for (int i = ty; i < 32; i += 8)
        t[i][tx] = W[(size_t)(kb + i) * N + nb + tx];
    __syncthreads();
    for (int i = ty; i < 32; i += 8) {
        int n = nb + i, k = kb + tx;
        float v = t[tx][i];
        __nv_bfloat16 h = __float2bfloat16_rn(v);
        __nv_bfloat16 l = __float2bfloat16_rn(v - __bfloat162float(h));
        __nv_bfloat16* d = Wt + (size_t)n * (3 * K) + k;
        d[0]     = h;
        d[K]     = h;
        d[2 * K] = l;
    }
}

// ---------------------------------------------------------------------------
// bf16 mma.sync GEMM, 3-stage cp.async pipeline, one barrier per chunk.
// mode 0: C = f32 out (+bias).   mode 1: hi/lo bf16 planes (+bias), Q scaled.
// ---------------------------------------------------------------------------
#define AST 72
#define STAGE_B  (128 * AST * 2)       // 18432 per operand tile
#define GEMM_SMEM (6 * STAGE_B)        // 110592 (3 stages x A,B)

__device__ __forceinline__ void g_load_tile(uint32_t sm_tile,
                                            const __nv_bfloat16* g, int k0, int tid)
{
#pragma unroll
    for (int i = 0; i < 4; i++) {
        int s = i * 256 + tid;
        int r = s >> 3, cg = s & 7;
        uint32_t dst = sm_tile + r * 144 + cg * 16;
        const void* src = g + (size_t)r * KP + k0 + cg * 8;
        asm volatile("cp.async.cg.shared.global [%0], [%1], 16;" :: "r"(dst), "l"(src));
    }
}

__global__ __launch_bounds__(256, 2) void mma_gemm_kernel(
    const __nv_bfloat16* __restrict__ A1, const __nv_bfloat16* __restrict__ Bt,
    const float* __restrict__ bias, float* __restrict__ C,
    __nv_bfloat16* __restrict__ hiP, __nv_bfloat16* __restrict__ loP,
    int Nt, int mode)
{
    extern __shared__ char smem[];
    const uint32_t sb = smem_u32(smem);
    const int tid = threadIdx.x, wid = tid >> 5, lane = tid & 31;
    const int m0 = blockIdx.y << 7, n0 = blockIdx.x << 7;
    const int wm = wid & 1, wn = wid >> 1;

    const __nv_bfloat16* Ag = A1 + (size_t)m0 * KP;
    const __nv_bfloat16* Bg = Bt + (size_t)n0 * KP;

    float acc[4][4][4];
#pragma unroll
    for (int i = 0; i < 4; i++)
#pragma unroll
        for (int j = 0; j < 4; j++)
#pragma unroll
            for (int r = 0; r < 4; r++) acc[i][j][r] = 0.f;

    const int a_row = (wm << 6) + (lane & 15);
    const int a_kof = (lane >> 4) << 3;
    const int b_row = (wn << 5) + (lane & 7) + (((lane >> 3) >> 1) << 3);
    const int b_kof = ((lane >> 3) & 1) << 3;

    // prologue: chunks 0,1 into stages 0,1
    g_load_tile(sb,                       Ag, 0, tid);
    g_load_tile(sb + 3 * STAGE_B,         Bg, 0, tid);
    asm volatile("cp.async.commit_group;" ::: "memory");
    g_load_tile(sb + STAGE_B,             Ag, GCH, tid);
    g_load_tile(sb + 3 * STAGE_B + STAGE_B, Bg, GCH, tid);
    asm volatile("cp.async.commit_group;" ::: "memory");

    int cur = 0, nxt = 2;     // compute stage, stage for chunk c+2
    for (int c = 0; c < NCH; c++) {
        if (c + 1 < NCH) asm volatile("cp.async.wait_group 1;" ::: "memory");
        else             asm volatile("cp.async.wait_group 0;" ::: "memory");
        __syncthreads();

        const uint32_t sAc = sb + cur * STAGE_B;
        const uint32_t sBc = sb + (3 + cur) * STAGE_B;
#pragma unroll
        for (int ks = 0; ks < 4; ks++) {
            const int kbase = ks << 4;
            uint32_t a[4][4];
#pragma unroll
            for (int mi = 0; mi < 4; mi++) {
                uint32_t addr = sAc + (uint32_t)(a_row + mi * 16) * 144
                              + (uint32_t)(kbase + a_kof) * 2;
                ldm_x4(addr, a[mi][0], a[mi][1], a[mi][2], a[mi][3]);
            }
            uint32_t b[4][2];
#pragma unroll
            for (int nb2 = 0; nb2 < 2; nb2++) {
                uint32_t addr = sBc + (uint32_t)(b_row + nb2 * 16) * 144
                              + (uint32_t)(kbase + b_kof) * 2;
                uint32_t t0, t1, t2, t3;
                ldm_x4(addr, t0, t1, t2, t3);
                b[nb2 * 2 + 0][0] = t0; b[nb2 * 2 + 0][1] = t1;
                b[nb2 * 2 + 1][0] = t2; b[nb2 * 2 + 1][1] = t3;
            }
#pragma unroll
            for (int mi = 0; mi < 4; mi++)
#pragma unroll
                for (int ni = 0; ni < 4; ni++)
                    mma16816(acc[mi][ni], a[mi], b[ni]);
        }

        if (c + 2 < NCH) {
            g_load_tile(sb + nxt * STAGE_B,       Ag, (c + 2) * GCH, tid);
            g_load_tile(sb + (3 + nxt) * STAGE_B, Bg, (c + 2) * GCH, tid);
            asm volatile("cp.async.commit_group;" ::: "memory");
        }
        cur = (cur == 2) ? 0 : cur + 1;
        nxt = (nxt == 2) ? 0 : nxt + 1;
    }

    const int r_top = m0 + (wm << 6) + (lane >> 2);
    const int c_base = n0 + (wn << 5) + ((lane & 3) << 1);
#pragma unroll
    for (int mi = 0; mi < 4; mi++) {
#pragma unroll
        for (int ni = 0; ni < 4; ni++) {
            const int col = c_base + ni * 8;
            const float b0 = bias[col], b1 = bias[col + 1];
            const int row0 = r_top + mi * 16;
            float v00 = acc[mi][ni][0] + b0, v01 = acc[mi][ni][1] + b1;
            float v10 = acc[mi][ni][2] + b0, v11 = acc[mi][ni][3] + b1;
            if (mode == 0) {
                float2 a0 = { v00, v01 }, a1v = { v10, v11 };
                *(float2*)&C[(size_t)row0 * Nt + col]       = a0;
                *(float2*)&C[(size_t)(row0 + 8) * Nt + col] = a1v;
            } else {
                if (col < CDIM) { v00 *= QSCALE; v01 *= QSCALE; v10 *= QSCALE; v11 *= QSCALE; }
                __nv_bfloat16 h00 = __float2bfloat16_rn(v00), h01 = __float2bfloat16_rn(v01);
                __nv_bfloat16 h10 = __float2bfloat16_rn(v10), h11 = __float2bfloat16_rn(v11);
                uint32_t hp0 = pack_bf(h00, h01), hp1 = pack_bf(h10, h11);
                uint32_t lp0 = pack_bf(__float2bfloat16_rn(v00 - __bfloat162float(h00)),
                                       __float2bfloat16_rn(v01 - __bfloat162float(h01)));
                uint32_t lp1 = pack_bf(__float2bfloat16_rn(v10 - __bfloat162float(h10)),
                                       __float2bfloat16_rn(v11 - __bfloat162float(h11)));
                *(uint32_t*)&hiP[(size_t)row0 * Nt + col]       = hp0;
                *(uint32_t*)&loP[(size_t)row0 * Nt + col]       = lp0;
                *(uint32_t*)&hiP[(size_t)(row0 + 8) * Nt + col] = hp1;
                *(uint32_t*)&loP[(size_t)(row0 + 8) * Nt + col] = lp1;
            }
        }
    }
}

// ---------------------------------------------------------------------------
// Tensor-core flash attention (bf16x3, causal). BM=64, BN=32, 128 threads,
// 2 CTAs/SM (smem 104.4 KB) so softmax of one CTA overlaps MMA of the other.
// Pre-split hi/lo QKV planes in gmem; double-buffered K/V stages.
// Output written directly in bf16 [hi | lo | hi] split layout for proj GEMM.
// ---------------------------------------------------------------------------
#define FR_STR  272                        // bytes per smem row (136 bf16)
#define OFF_QH  0
#define OFF_QL  (64 * FR_STR)              // 17408
#define OFF_KV0 (2 * 64 * FR_STR)          // 34816
#define KV_STAGE (4 * 32 * FR_STR)         // 34816 (KH,KL,VH,VL x 32 rows)
#define SOFF_KH 0
#define SOFF_KL (32 * FR_STR)
#define SOFF_VH (2 * 32 * FR_STR)
#define SOFF_VL (3 * 32 * FR_STR)
#define FLASH_SMEM (OFF_KV0 + 2 * KV_STAGE)  // 104448

// one 32x128 bf16 plane tile: 32 rows x 16 chunks of 16B; 4 chunks/thread
__device__ __forceinline__ void stage_plane32(uint32_t dst,
                                              const __nv_bfloat16* src, int tid)
{
#pragma unroll
    for (int i = 0; i < 4; i++) {
        int s = i * 128 + tid;
        int r = s >> 4, c = s & 15;
        asm volatile("cp.async.cg.shared.global [%0], [%1], 16;"
                     :: "r"(dst + r * FR_STR + c * 16),
                        "l"(src + (size_t)r * (3 * CDIM) + c * 8));
    }
}

__global__ __launch_bounds__(128, 2) void flash_mma_kernel(
    const __nv_bfloat16* __restrict__ qh, const __nv_bfloat16* __restrict__ ql,
    __nv_bfloat16* __restrict__ a1out)
{
    extern __shared__ char smc[];
    const uint32_t sb = smem_u32(smc);
    const int tid = threadIdx.x, w = tid >> 5, lane = tid & 31;
    const int b = blockIdx.y / NH, h = blockIdx.y % NH;
    const int p = gridDim.x - 1 - blockIdx.x;     // heaviest first
    const int qm0 = p << 6;                       // 64 q-rows per CTA

    const __nv_bfloat16* qhB = qh + (size_t)(b * S_LEN) * (3 * CDIM) + h * HD;
    const __nv_bfloat16* qlB = ql + (size_t)(b * S_LEN) * (3 * CDIM) + h * HD;
    const int nkb = 2 * p + 2;                    // key blocks of 32

    // group 0: Q tiles (hi+lo, 64 rows) + KV stage 0
    {
        const __nv_bfloat16* qsrc_h = qhB + (size_t)qm0 * (3 * CDIM);
        const __nv_bfloat16* qsrc_l = qlB + (size_t)qm0 * (3 * CDIM);
#pragma unroll
        for (int i = 0; i < 8; i++) {
            int s = i * 128 + tid;
            int r = s >> 4, c = s & 15;
            asm volatile("cp.async.cg.shared.global [%0], [%1], 16;"
                         :: "r"(sb + OFF_QH + r * FR_STR + c * 16),
                            "l"(qsrc_h + (size_t)r * (3 * CDIM) + c * 8));
            asm volatile("cp.async.cg.shared.global [%0], [%1], 16;"
                         :: "r"(sb + OFF_QL + r * FR_STR + c * 16),
                            "l"(qsrc_l + (size_t)r * (3 * CDIM) + c * 8));
        }
        const uint32_t st0 = sb + OFF_KV0;
        stage_plane32(st0 + SOFF_KH, qhB + CDIM, tid);
        stage_plane32(st0 + SOFF_KL, qlB + CDIM, tid);
        stage_plane32(st0 + SOFF_VH, qhB + 2 * CDIM, tid);
        stage_plane32(st0 + SOFF_VL, qlB + 2 * CDIM, tid);
        asm volatile("cp.async.commit_group;" ::: "memory");
    }

    float m_i[2] = { -1e30f, -1e30f }, l_i[2] = { 0.f, 0.f };
    float o[16][4];
#pragma unroll
    for (int n = 0; n < 16; n++)
#pragma unroll
        for (int r = 0; r < 4; r++) o[n][r] = 0.f;

    const int a_row = (w << 4) + (lane & 15);
    const int a_k8  = (lane >> 4) << 3;
    const int b_row = (lane & 7) + (((lane >> 3) >> 1) << 3);
    const int b_k8  = ((lane >> 3) & 1) << 3;
    const int v_row = lane & 15;
    const int v_n8  = (lane >> 4) << 3;

    const int row_t = qm0 + (w << 4) + (lane >> 2);
    const int col_q = (lane & 3) << 1;

    for (int kb = 0; kb < nkb; kb++) {
        if (kb + 1 < nkb) {
            const uint32_t stn = sb + OFF_KV0 + ((kb + 1) & 1) * KV_STAGE;
            const size_t roff = (size_t)((kb + 1) << 5) * (3 * CDIM);
            stage_plane32(stn + SOFF_KH, qhB + roff + CDIM, tid);
            stage_plane32(stn + SOFF_KL, qlB + roff + CDIM, tid);
            stage_plane32(stn + SOFF_VH, qhB + roff + 2 * CDIM, tid);
            stage_plane32(stn + SOFF_VL, qlB + roff + 2 * CDIM, tid);
            asm volatile("cp.async.commit_group;" ::: "memory");
            asm volatile("cp.async.wait_group 1;" ::: "memory");
        } else {
            asm volatile("cp.async.wait_group 0;" ::: "memory");
        }
        __syncthreads();
        const uint32_t st = sb + OFF_KV0 + (kb & 1) * KV_STAGE;

        // ---- S = Q'K'^T (3-term bf16), 64x32 ----
        float s[4][4];
#pragma unroll
        for (int n = 0; n < 4; n++)
#pragma unroll
            for (int r = 0; r < 4; r++) s[n][r] = 0.f;

#pragma unroll
        for (int kt = 0; kt < 8; kt++) {
            const uint32_t koff = (uint32_t)(kt * 16 + a_k8) * 2;
            uint32_t aH[4], aL[4];
            ldm_x4(sb + OFF_QH + (uint32_t)a_row * FR_STR + koff,
                   aH[0], aH[1], aH[2], aH[3]);
            ldm_x4(sb + OFF_QL + (uint32_t)a_row * FR_STR + koff,
                   aL[0], aL[1], aL[2], aL[3]);
            const uint32_t kboff = (uint32_t)(kt * 16 + b_k8) * 2;
#pragma unroll
            for (int nb = 0; nb < 2; nb++) {
                uint32_t h0, h1, h2, h3, u0, u1, u2, u3;
                ldm_x4(st + SOFF_KH + (uint32_t)(nb * 16 + b_row) * FR_STR + kboff,
                       h0, h1, h2, h3);
                ldm_x4(st + SOFF_KL + (uint32_t)(nb * 16 + b_row) * FR_STR + kboff,
                       u0, u1, u2, u3);
                uint32_t bh0[2] = { h0, h1 }, bh1[2] = { h2, h3 };
                uint32_t bl0[2] = { u0, u1 }, bl1[2] = { u2, u3 };
                mma16816(s[2 * nb],     aH, bh0);
                mma16816(s[2 * nb],     aL, bh0);
                mma16816(s[2 * nb],     aH, bl0);
                mma16816(s[2 * nb + 1], aH, bh1);
                mma16816(s[2 * nb + 1], aL, bh1);
                mma16816(s[2 * nb + 1], aH, bl1);
            }
        }

        // ---- causal mask (diagonal key blocks only) ----
        if (kb >= 2 * p) {
            const int col0 = (kb << 5) + col_q;
#pragma unroll
            for (int n = 0; n < 4; n++) {
                const int c = col0 + n * 8;
                if (c     > row_t)     s[n][0] = -1e30f;
                if (c + 1 > row_t)     s[n][1] = -1e30f;
                if (c     > row_t + 8) s[n][2] = -1e30f;
                if (c + 1 > row_t + 8) s[n][3] = -1e30f;
            }
        }

        // ---- online softmax (fp32) ----
        float alpha[2];
#pragma unroll
        for (int hf = 0; hf < 2; hf++) {
            float mx = -1e30f;
#pragma unroll
            for (int n = 0; n < 4; n++)
                mx = fmaxf(mx, fmaxf(s[n][2 * hf], s[n][2 * hf + 1]));
            mx = fmaxf(mx, __shfl_xor_sync(0xffffffffu, mx, 1));
            mx = fmaxf(mx, __shfl_xor_sync(0xffffffffu, mx, 2));
            const float mnew = fmaxf(m_i[hf], mx);
            alpha[hf] = __expf(m_i[hf] - mnew);
            m_i[hf] = mnew;
            float rs = 0.f;
#pragma unroll
            for (int n = 0; n < 4; n++) {
                s[n][2 * hf]     = __expf(s[n][2 * hf]     - mnew);
                s[n][2 * hf + 1] = __expf(s[n][2 * hf + 1] - mnew);
                rs += s[n][2 * hf] + s[n][2 * hf + 1];
            }
            rs += __shfl_xor_sync(0xffffffffu, rs, 1);
            rs += __shfl_xor_sync(0xffffffffu, rs, 2);
            l_i[hf] = l_i[hf] * alpha[hf] + rs;
        }
#pragma unroll
        for (int n = 0; n < 16; n++) {
            o[n][0] *= alpha[0]; o[n][1] *= alpha[0];
            o[n][2] *= alpha[1]; o[n][3] *= alpha[1];
        }

        // ---- P -> bf16 hi/lo A-fragments ----
        uint32_t aPh[2][4], aPl[2][4];
#pragma unroll
        for (int kt = 0; kt < 2; kt++) {
#pragma unroll
            for (int half = 0; half < 2; half++) {
                const int t = 2 * kt + half;
                __nv_bfloat16 h0 = __float2bfloat16_rn(s[t][0]);
                __nv_bfloat16 h1 = __float2bfloat16_rn(s[t][1]);
                __nv_bfloat16 h2 = __float2bfloat16_rn(s[t][2]);
                __nv_bfloat16 h3 = __float2bfloat16_rn(s[t][3]);
                __nv_bfloat16 l0 = __float2bfloat16_rn(s[t][0] - __bfloat162float(h0));
                __nv_bfloat16 l1 = __float2bfloat16_rn(s[t][1] - __bfloat162float(h1));
                __nv_bfloat16 l2 = __float2bfloat16_rn(s[t][2] - __bfloat162float(h2));
                __nv_bfloat16 l3 = __float2bfloat16_rn(s[t][3] - __bfloat162float(h3));
                aPh[kt][2 * half + 0] = pack_bf(h0, h1);
                aPh[kt][2 * half + 1] = pack_bf(h2, h3);
                aPl[kt][2 * half + 0] = pack_bf(l0, l1);
                aPl[kt][2 * half + 1] = pack_bf(l2, l3);
            }
        }

        // ---- O += P'V' (3-term bf16), k=32 ----
#pragma unroll
        for (int kt = 0; kt < 2; kt++) {
            const uint32_t vro = (uint32_t)(kt * 16 + v_row) * FR_STR;
#pragma unroll
            for (int nv = 0; nv < 8; nv++) {
                const uint32_t noff = (uint32_t)(nv * 16 + v_n8) * 2;
                uint32_t h0, h1, h2, h3, u0, u1, u2, u3;
                ldm_x4_t(st + SOFF_VH + vro + noff, h0, h1, h2, h3);
                ldm_x4_t(st + SOFF_VL + vro + noff, u0, u1, u2, u3);
                uint32_t bh0[2] = { h0, h1 }, bh1[2] = { h2, h3 };
                uint32_t bl0[2] = { u0, u1 }, bl1[2] = { u2, u3 };
                mma16816(o[2 * nv],     aPh[kt], bh0);
                mma16816(o[2 * nv],     aPl[kt], bh0);
                mma16816(o[2 * nv],     aPh[kt], bl0);
                mma16816(o[2 * nv + 1], aPh[kt], bh1);
                mma16816(o[2 * nv + 1], aPl[kt], bh1);
                mma16816(o[2 * nv + 1], aPh[kt], bl1);
            }
        }
        __syncthreads();   // compute done before next iter overwrites stage
    }

    // ---- epilogue: write O directly in split [hi | lo | hi] layout ----
    const float inv0 = 1.f / l_i[0], inv1 = 1.f / l_i[1];
    __nv_bfloat16* ab = a1out + (size_t)(b * S_LEN) * KP + h * HD;
#pragma unroll
    for (int n = 0; n < 16; n++) {
        const int col = n * 8 + col_q;
        float v00 = o[n][0] * inv0, v01 = o[n][1] * inv0;
        float v10 = o[n][2] * inv1, v11 = o[n][3] * inv1;
        __nv_bfloat16 h00 = __float2bfloat16_rn(v00), h01 = __float2bfloat16_rn(v01);
        __nv_bfloat16 h10 = __float2bfloat16_rn(v10), h11 = __float2bfloat16_rn(v11);
        uint32_t hp0 = pack_bf(h00, h01), hp1 = pack_bf(h10, h11);
        uint32_t lp0 = pack_bf(__float2bfloat16_rn(v00 - __bfloat162float(h00)),
                               __float2bfloat16_rn(v01 - __bfloat162float(h01)));
        uint32_t lp1 = pack_bf(__float2bfloat16_rn(v10 - __bfloat162float(h10)),
                               __float2bfloat16_rn(v11 - __bfloat162float(h11)));
        __nv_bfloat16* p0 = ab + (size_t)row_t * KP + col;
        __nv_bfloat16* p1 = ab + (size_t)(row_t + 8) * KP + col;
        *(uint32_t*)(p0)            = hp0;
        *(uint32_t*)(p0 + CDIM)     = lp0;
        *(uint32_t*)(p0 + 2 * CDIM) = hp0;
        *(uint32_t*)(p1)            = hp1;
        *(uint32_t*)(p1 + CDIM)     = lp1;
        *(uint32_t*)(p1 + 2 * CDIM) = hp1;
    }
}

// ---------------------------------------------------------------------------
extern "C" void kernel_launch(void* const* d_in, const int* in_sizes, int n_in,
                              void* d_out, int out_size)
{
    const float* x      = (const float*)d_in[0];
    const float* w_attn = (const float*)d_in[1];
    const float* b_attn = (const float*)d_in[2];
    const float* w_proj = (const float*)d_in[3];
    const float* b_proj = (const float*)d_in[4];
    float* out = (float*)d_out;

    __nv_bfloat16 *a1 = nullptr, *wt1 = nullptr, *wt2 = nullptr, *qh = nullptr, *ql = nullptr;
    cudaGetSymbolAddress((void**)&a1,  g_a1);
    cudaGetSymbolAddress((void**)&wt1, g_wt1);
    cudaGetSymbolAddress((void**)&wt2, g_wt2);
    cudaGetSymbolAddress((void**)&qh,  g_qh);
    cudaGetSymbolAddress((void**)&ql,  g_ql);

    cudaFuncSetAttribute(mma_gemm_kernel,
                         cudaFuncAttributeMaxDynamicSharedMemorySize, GEMM_SMEM);
    cudaFuncSetAttribute(flash_mma_kernel,
                         cudaFuncAttributeMaxDynamicSharedMemorySize, FLASH_SMEM);

    // --- Stage 1: QKV = x @ w_attn + b -> hi/lo planes (Q pre-scaled) ---
    asplit_kernel<<<(MTOT * CDIM + 255) / 256, 256>>>(x, a1, MTOT * CDIM, CDIM);
    {
        dim3 gt(CDIM / 32, (3 * CDIM) / 32), bt(32, 8);
        wsplit_kernel<<<gt, bt>>>(w_attn, wt1, CDIM, 3 * CDIM);
    }
    {
        dim3 g(3 * CDIM / 128, MTOT / 128);
        mma_gemm_kernel<<<g, 256, GEMM_SMEM>>>(a1, wt1, b_attn, nullptr,
                                               qh, ql, 3 * CDIM, 1);
    }

    // --- Stage 2: causal flash attention (bf16x3), 2 CTA/SM ---
    {
        dim3 g(S_LEN / 64, NB * NH);
        flash_mma_kernel<<<g, 128, FLASH_SMEM>>>(qh, ql, a1);
    }

    // --- Stage 3: out = att @ w_proj + b (att already split in a1) ---
    {
        dim3 gt(CDIM / 32, CDIM / 32), bt(32, 8);
        wsplit_kernel<<<gt, bt>>>(w_proj, wt2, CDIM, CDIM);
    }
    {
        dim3 g(CDIM / 128, MTOT / 128);
        mma_gemm_kernel<<<g, 256, GEMM_SMEM>>>(a1, wt2, b_proj, out,
                                               nullptr, nullptr, CDIM, 0);
    }
}